// round 7
// baseline (speedup 1.0000x reference)
#include <cuda_runtime.h>
#include <cuda_fp16.h>
#include <cstdint>

// ---------------------------------------------------------------------------
// HiPPO-LegT: chunked convolution + one big GEMM.
// Main GEMM on mma.sync fp16 (2-term split: Ah*Bh + Al*Bh, fp32 acc).
//
//  out[l, r, n] = sum_{k<=l} (A^{l-k} B)[n] * f[r, k]   (r = b*64+m, R=512)
//  Chunk T=128, C=8, v_j = A^j B:
//    out(i*T+t) = sum_{k<=t} v_{t-k} f[r,iT+k] + A^{t+1} h_{i-1}
//  One GEMM: Out(4096 x 32768) = X(4096 x 384) @ Kmat(384 x 32768)
// ---------------------------------------------------------------------------

#define N_ST   256
#define T_CH   128
#define MAT    65536
#define NCHUNK 6
#define AB_BLK 16384              // bytes: 128 rows x 64 k fp16 (swizzled)
#define BB_BLK 32768              // bytes: 256 rows x 64 k fp16 (swizzled)

// main mma kernel smem: per stage [Ah 16K][Al 16K][B 32K], 3 stages
#define ST_AL  16384
#define ST_B   32768
#define ST_SZ  65536
#define NSTG   3
#define SMEM_SZ (NSTG * ST_SZ)

// ---- device scratch ----
__device__ __align__(256) float g_Apow[129 * MAT];     // A^1..A^128 at 1..128
__device__ __align__(256) float g_V[T_CH * N_ST];      // v_j = A^j B
__device__ __align__(256) float g_Qp[8 * MAT];         // (A^128)^p, p=2..7
__device__ __align__(256) float g_S[8 * 512 * N_ST];
__device__ __align__(256) float g_H[8 * 512 * N_ST];
__device__ __align__(256) __half g_Ah[(size_t)32 * NCHUNK * 8192];
__device__ __align__(256) __half g_Al[(size_t)32 * NCHUNK * 8192];
__device__ __align__(256) __half g_Bh[(size_t)128 * NCHUNK * 16384];

// ---------------------------------------------------------------------------
__device__ __forceinline__ uint32_t smem_u32(const void* p) {
    uint32_t a;
    asm("{ .reg .u64 t; cvta.to.shared.u64 t, %1; cvt.u32.u64 %0, t; }" : "=r"(a) : "l"(p));
    return a;
}
__device__ __forceinline__ void cp16(uint32_t s, const void* g) {
    asm volatile("cp.async.cg.shared.global [%0], [%1], 16;" :: "r"(s), "l"(g));
}
#define CP_COMMIT() asm volatile("cp.async.commit_group;" ::: "memory")
#define CP_WAIT(n)  asm volatile("cp.async.wait_group %0;" :: "n"(n) : "memory")

__device__ __forceinline__ void ldm4(uint32_t* r, uint32_t addr) {
    asm volatile("ldmatrix.sync.aligned.m8n8.x4.shared.b16 {%0,%1,%2,%3}, [%4];"
                 : "=r"(r[0]), "=r"(r[1]), "=r"(r[2]), "=r"(r[3]) : "r"(addr));
}
__device__ __forceinline__ void mma16816(float* d, const uint32_t* a,
                                         uint32_t b0, uint32_t b1) {
    asm volatile(
        "mma.sync.aligned.m16n8k16.row.col.f32.f16.f16.f32 "
        "{%0,%1,%2,%3}, {%4,%5,%6,%7}, {%8,%9}, {%0,%1,%2,%3};"
        : "+f"(d[0]), "+f"(d[1]), "+f"(d[2]), "+f"(d[3])
        : "r"(a[0]), "r"(a[1]), "r"(a[2]), "r"(a[3]), "r"(b0), "r"(b1));
}

__device__ __forceinline__ uint32_t swz(uint32_t off) { return off ^ ((off >> 3) & 0x70); }

__device__ __forceinline__ unsigned short hbits(float x) {
    __half h = __float2half_rn(x);
    return *reinterpret_cast<unsigned short*>(&h);
}
__device__ __forceinline__ void split2h(float x, unsigned short& h, unsigned short& l) {
    __half hh = __float2half_rn(x);
    h = *reinterpret_cast<unsigned short*>(&hh);
    l = hbits(x - __half2float(hh));
}

// ---------------------------------------------------------------------------
// prologue (fp32 SIMT) — exact structure that passed in round 4
// ---------------------------------------------------------------------------
__global__ void init_a_kernel(const float* __restrict__ A) {
    int idx = blockIdx.x * blockDim.x + threadIdx.x;
    if (idx < MAT) g_Apow[MAT + idx] = A[idx];
}

__device__ __forceinline__ void gemm64_body(const float* __restrict__ Am,
                                            const float* __restrict__ Bm,
                                            float* __restrict__ Cm,
                                            const float* __restrict__ bias) {
    __shared__ float As[16][64];
    __shared__ float Bs[16][64];
    const int brow = blockIdx.y * 64;
    const int bcol = blockIdx.x * 64;
    const int tid = threadIdx.x;
    const int tr = tid >> 4, tc = tid & 15;
    const int alr = tid >> 2, alc = (tid & 3) * 4;
    const int blr = tid >> 4, blc = (tid & 15) * 4;
    float acc[4][4] = {};
    for (int k0 = 0; k0 < 256; k0 += 16) {
        float4 a4 = *(const float4*)&Am[(brow + alr) * 256 + k0 + alc];
        As[alc + 0][alr] = a4.x; As[alc + 1][alr] = a4.y;
        As[alc + 2][alr] = a4.z; As[alc + 3][alr] = a4.w;
        float4 b4 = *(const float4*)&Bm[(k0 + blr) * 256 + bcol + blc];
        *(float4*)&Bs[blr][blc] = b4;
        __syncthreads();
#pragma unroll
        for (int k = 0; k < 16; k++) {
            float av[4], bv[4];
            *(float4*)&av[0] = *(const float4*)&As[k][tr * 4];
            *(float4*)&bv[0] = *(const float4*)&Bs[k][tc * 4];
#pragma unroll
            for (int ii = 0; ii < 4; ii++)
#pragma unroll
                for (int jj = 0; jj < 4; jj++)
                    acc[ii][jj] += av[ii] * bv[jj];
        }
        __syncthreads();
    }
#pragma unroll
    for (int ii = 0; ii < 4; ii++) {
        int rr = brow + tr * 4 + ii;
        int cc = bcol + tc * 4;
        float4 v;
        v.x = acc[ii][0]; v.y = acc[ii][1]; v.z = acc[ii][2]; v.w = acc[ii][3];
        if (bias) {
            float4 b = *(const float4*)&bias[rr * 256 + cc];
            v.x += b.x; v.y += b.y; v.z += b.z; v.w += b.w;
        }
        *(float4*)&Cm[rr * 256 + cc] = v;
    }
}

__global__ void pow_double_kernel(int d) {
    int j = blockIdx.z + 1;
    gemm64_body(g_Apow + (size_t)d * MAT, g_Apow + (size_t)j * MAT,
                g_Apow + (size_t)(d + j) * MAT, nullptr);
}

// Qp chain: Qp[p] = (A^128)^p
__global__ void qp2_kernel() {
    gemm64_body(g_Apow + (size_t)128 * MAT, g_Apow + (size_t)128 * MAT,
                g_Qp + (size_t)2 * MAT, nullptr);
}
__global__ void qp34_kernel() {
    if (blockIdx.z == 0)
        gemm64_body(g_Qp + (size_t)2 * MAT, g_Apow + (size_t)128 * MAT,
                    g_Qp + (size_t)3 * MAT, nullptr);
    else
        gemm64_body(g_Qp + (size_t)2 * MAT, g_Qp + (size_t)2 * MAT,
                    g_Qp + (size_t)4 * MAT, nullptr);
}
__global__ void qp567_kernel() {
    const float* rhs = (blockIdx.z == 0) ? g_Apow + (size_t)128 * MAT
                                         : g_Qp + (size_t)(blockIdx.z + 1) * MAT;
    gemm64_body(g_Qp + (size_t)4 * MAT, rhs,
                g_Qp + (size_t)(5 + blockIdx.z) * MAT, nullptr);
}

__global__ void v_kernel(const float* __restrict__ Bv) {
    __shared__ float bs[256];
    int j = blockIdx.x, n = threadIdx.x;
    bs[n] = Bv[n];
    __syncthreads();
    if (j == 0) { g_V[n] = bs[n]; return; }
    const float* Am = g_Apow + (size_t)j * MAT;
    float s = 0.f;
#pragma unroll 8
    for (int m = 0; m < 256; m++) s += Am[n * 256 + m] * bs[m];
    g_V[j * 256 + n] = s;
}

__global__ void s_kernel(const float* __restrict__ inp) {
    __shared__ float fs[128];
    int r = blockIdx.x, i = blockIdx.y, n = threadIdx.x;
    if (n < 128) fs[n] = inp[r * 1024 + i * T_CH + n];
    __syncthreads();
    float s = 0.f;
#pragma unroll 4
    for (int k = 0; k < 128; k++)
        s += g_V[(127 - k) * 256 + n] * fs[k];
    g_S[(i * 512 + r) * 256 + n] = s;
    if (i == 0) g_H[r * 256 + n] = s;
}

// H[i] = S[i] + sum_{j<i} S[j] * Qp[i-j]^T     (one parallel launch, i=1..7)
__global__ void combine_all_kernel() {
    __shared__ float As[16][64];
    __shared__ float Bs[16][64];
    const int i = blockIdx.z + 1;
    const int brow = blockIdx.y * 64;
    const int bcol = blockIdx.x * 64;
    const int tid = threadIdx.x;
    const int tr = tid >> 4, tc = tid & 15;
    const int alr = tid >> 2, alc = (tid & 3) * 4;
    const int bc = tid >> 2, bk = (tid & 3) * 4;
    float acc[4][4] = {};
    for (int j = 0; j < i; j++) {
        const int p = i - j;
        const float* Qp = (p == 1) ? g_Apow + (size_t)128 * MAT
                                   : g_Qp + (size_t)p * MAT;
        const float* Sj = g_S + (size_t)j * (512 * 256);
        for (int k0 = 0; k0 < 256; k0 += 16) {
            float4 a4 = *(const float4*)&Sj[(brow + alr) * 256 + k0 + alc];
            As[alc + 0][alr] = a4.x; As[alc + 1][alr] = a4.y;
            As[alc + 2][alr] = a4.z; As[alc + 3][alr] = a4.w;
            float4 q4 = *(const float4*)&Qp[(size_t)(bcol + bc) * 256 + k0 + bk];
            Bs[bk + 0][bc] = q4.x; Bs[bk + 1][bc] = q4.y;
            Bs[bk + 2][bc] = q4.z; Bs[bk + 3][bc] = q4.w;
            __syncthreads();
#pragma unroll
            for (int k = 0; k < 16; k++) {
                float av[4], bv[4];
                *(float4*)&av[0] = *(const float4*)&As[k][tr * 4];
                *(float4*)&bv[0] = *(const float4*)&Bs[k][tc * 4];
#pragma unroll
                for (int ii = 0; ii < 4; ii++)
#pragma unroll
                    for (int jj = 0; jj < 4; jj++)
                        acc[ii][jj] += av[ii] * bv[jj];
            }
            __syncthreads();
        }
    }
    float* Hout = g_H + (size_t)i * (512 * 256);
    const float* Si = g_S + (size_t)i * (512 * 256);
#pragma unroll
    for (int ii = 0; ii < 4; ii++) {
        int rr = brow + tr * 4 + ii;
        int cc = bcol + tc * 4;
        float4 b = *(const float4*)&Si[rr * 256 + cc];
        float4 v;
        v.x = acc[ii][0] + b.x; v.y = acc[ii][1] + b.y;
        v.z = acc[ii][2] + b.z; v.w = acc[ii][3] + b.w;
        *(float4*)&Hout[rr * 256 + cc] = v;
    }
}

// ---------------------------------------------------------------------------
// limb-split packers (fp16), SW128-swizzled, exact smem image.
// ---------------------------------------------------------------------------
__global__ void b_limbs_kernel() {
    const int blk = blockIdx.x;            // t*6 + kc
    const int t = blk / NCHUNK, kc = blk % NCHUNK;
    const int tid = threadIdx.x;
    const int kk0 = (tid & 15) * 4;
    char* dh = (char*)g_Bh + (size_t)blk * BB_BLK;
    for (int it = 0; it < 16; it++) {
        int n = it * 16 + (tid >> 4);
        float v[4];
        if (kc < 2) {
            int k0 = kc * 64 + kk0;
#pragma unroll
            for (int q = 0; q < 4; q++) {
                int k = k0 + q;
                v[q] = (k <= t) ? g_V[(t - k) * 256 + n] : 0.f;
            }
        } else {
            int m0 = kc * 64 + kk0 - 128;
            float4 a4 = *(const float4*)&g_Apow[(size_t)(t + 1) * MAT + n * 256 + m0];
            v[0] = a4.x; v[1] = a4.y; v[2] = a4.z; v[3] = a4.w;
        }
        uint2 ph;
        ph.x = (uint32_t)hbits(v[0]) | ((uint32_t)hbits(v[1]) << 16);
        ph.y = (uint32_t)hbits(v[2]) | ((uint32_t)hbits(v[3]) << 16);
        uint32_t off = swz((uint32_t)(n * 128 + kk0 * 2));
        *(uint2*)(dh + off) = ph;
    }
}

__global__ void a_limbs_kernel(const float* __restrict__ inp) {
    const int blk = blockIdx.x;            // rt*6 + kc
    const int rt = blk / NCHUNK, kc = blk % NCHUNK;
    const int i = rt >> 2;
    const int tid = threadIdx.x;
    const int kk0 = (tid & 15) * 4;
    char* dh = (char*)g_Ah + (size_t)blk * AB_BLK;
    char* dl = (char*)g_Al + (size_t)blk * AB_BLK;
    for (int it = 0; it < 8; it++) {
        int row = it * 16 + (tid >> 4);
        int r = (rt & 3) * 128 + row;
        float v[4];
        if (kc < 2) {
            float4 f4 = *(const float4*)&inp[r * 1024 + i * 128 + kc * 64 + kk0];
            v[0] = f4.x; v[1] = f4.y; v[2] = f4.z; v[3] = f4.w;
        } else if (i == 0) {
            v[0] = v[1] = v[2] = v[3] = 0.f;
        } else {
            float4 f4 = *(const float4*)&g_H[(size_t)((i - 1) * 512 + r) * 256 +
                                             (kc - 2) * 64 + kk0];
            v[0] = f4.x; v[1] = f4.y; v[2] = f4.z; v[3] = f4.w;
        }
        unsigned short h[4], l[4];
#pragma unroll
        for (int q = 0; q < 4; q++) split2h(v[q], h[q], l[q]);
        uint2 ph, pl;
        ph.x = (uint32_t)h[0] | ((uint32_t)h[1] << 16);
        ph.y = (uint32_t)h[2] | ((uint32_t)h[3] << 16);
        pl.x = (uint32_t)l[0] | ((uint32_t)l[1] << 16);
        pl.y = (uint32_t)l[2] | ((uint32_t)l[3] << 16);
        uint32_t off = swz((uint32_t)(row * 128 + kk0 * 2));
        *(uint2*)(dh + off) = ph;
        *(uint2*)(dl + off) = pl;
    }
}

// ---------------------------------------------------------------------------
// Main GEMM: fp16 2-term mma.sync. CTA = 128x256 out tile (full t column),
// 512 threads (16 warps, 32x64 warp tiles), 3-stage cp.async pipeline,
// causal zero-chunk skipped. grid (128 t-tiles, 32 row tiles).
// ---------------------------------------------------------------------------
__global__ __launch_bounds__(512, 1) void main_mma_kernel(float* __restrict__ out) {
    extern __shared__ char smem[];
    const uint32_t sb = smem_u32(smem);
    const int tid = threadIdx.x;
    const int wid = tid >> 5;
    const int lane = tid & 31;
    const int t = blockIdx.x;           // col tile = t (full 256 cols)
    const int by = blockIdx.y;          // row tile

    const int m0w = (wid & 3) * 32;
    const int n0w = (wid >> 2) * 64;

    // chunk list: skip kc=1 when t<64 (all-zero causal block)
    int clist[6] = {0, 1, 2, 3, 4, 5};
    int nch = 6;
    if (t < 64) { clist[1] = 2; clist[2] = 3; clist[3] = 4; clist[4] = 5; nch = 5; }

    const char* Asrc_h = (const char*)g_Ah + (size_t)by * NCHUNK * AB_BLK;
    const char* Asrc_l = (const char*)g_Al + (size_t)by * NCHUNK * AB_BLK;
    const char* Bsrc   = (const char*)g_Bh + (size_t)t * NCHUNK * BB_BLK;

    const uint32_t cpo = (uint32_t)tid * 16;   // < 8192

    uint32_t aoff[2][4];
    uint32_t boff[4][4];
    {
        const uint32_t arow = (uint32_t)(m0w + (lane & 15)) * 128;
        const uint32_t khalf = (uint32_t)(lane >> 4) * 16;
#pragma unroll
        for (int mt = 0; mt < 2; mt++)
#pragma unroll
            for (int ks = 0; ks < 4; ks++)
                aoff[mt][ks] = swz(arow + (uint32_t)mt * 2048 + khalf + ks * 32);
        const uint32_t brow = (uint32_t)(n0w + (lane & 15)) * 128;
#pragma unroll
        for (int ng = 0; ng < 4; ng++)
#pragma unroll
            for (int ks = 0; ks < 4; ks++)
                boff[ng][ks] = swz(brow + (uint32_t)ng * 2048 + khalf + ks * 32);
    }

    float acc[2][8][4];
#pragma unroll
    for (int mt = 0; mt < 2; mt++)
#pragma unroll
        for (int nt = 0; nt < 8; nt++)
#pragma unroll
            for (int q = 0; q < 4; q++) acc[mt][nt][q] = 0.f;

#define LOAD_STAGE(kc, st)                                                      \
    do {                                                                        \
        uint32_t s0 = sb + (uint32_t)(st) * ST_SZ;                              \
        const char* ga = Asrc_h + (size_t)(kc) * AB_BLK;                        \
        const char* gb = Asrc_l + (size_t)(kc) * AB_BLK;                        \
        const char* gc = Bsrc + (size_t)(kc) * BB_BLK;                          \
        cp16(s0 + cpo, ga + cpo);                                               \
        cp16(s0 + 8192 + cpo, ga + 8192 + cpo);                                 \
        cp16(s0 + ST_AL + cpo, gb + cpo);                                       \
        cp16(s0 + ST_AL + 8192 + cpo, gb + 8192 + cpo);                         \
        _Pragma("unroll")                                                       \
        for (int q = 0; q < 4; q++)                                             \
            cp16(s0 + ST_B + q * 8192 + cpo, gc + q * 8192 + cpo);              \
        CP_COMMIT();                                                            \
    } while (0)

    LOAD_STAGE(clist[0], 0);
    LOAD_STAGE(clist[1], 1);

    for (int j = 0; j < nch; j++) {
        if (j + NSTG - 1 < nch) {
            LOAD_STAGE(clist[j + NSTG - 1], (j + NSTG - 1) % NSTG);
            CP_WAIT(2);
        } else if (j == nch - 2) {
            CP_WAIT(1);
        } else {
            CP_WAIT(0);
        }
        __syncthreads();
        const uint32_t st = sb + (uint32_t)(j % NSTG) * ST_SZ;
#pragma unroll
        for (int ks = 0; ks < 4; ks++) {
            uint32_t ah[2][4], al[2][4];
#pragma unroll
            for (int mt = 0; mt < 2; mt++) {
                ldm4(ah[mt], st + aoff[mt][ks]);
                ldm4(al[mt], st + ST_AL + aoff[mt][ks]);
            }
#pragma unroll
            for (int ng = 0; ng < 4; ng++) {
                uint32_t bh[4];
                ldm4(bh, st + ST_B + boff[ng][ks]);
#pragma unroll
                for (int mt = 0; mt < 2; mt++) {
                    mma16816(acc[mt][2 * ng + 0], ah[mt], bh[0], bh[2]);
                    mma16816(acc[mt][2 * ng + 1], ah[mt], bh[1], bh[3]);
                    mma16816(acc[mt][2 * ng + 0], al[mt], bh[0], bh[2]);
                    mma16816(acc[mt][2 * ng + 1], al[mt], bh[1], bh[3]);
                }
            }
        }
        __syncthreads();
    }
#undef LOAD_STAGE

    // epilogue: out[(i*128 + t)*131072 + r*256 + n]
    const int i_ch = by >> 2;
    float* ob = out + (size_t)(i_ch * 128 + t) * 131072;
    const int rbase = (by & 3) * 128 + m0w + (lane >> 2);
    const int cbase = n0w + (lane & 3) * 2;
#pragma unroll
    for (int mt = 0; mt < 2; mt++) {
        const int r0 = rbase + mt * 16;
#pragma unroll
        for (int nt = 0; nt < 8; nt++) {
            const int c = cbase + nt * 8;
            float2 v0 = make_float2(acc[mt][nt][0], acc[mt][nt][1]);
            float2 v1 = make_float2(acc[mt][nt][2], acc[mt][nt][3]);
            __stcs((float2*)(ob + (size_t)r0 * 256 + c), v0);
            __stcs((float2*)(ob + (size_t)(r0 + 8) * 256 + c), v1);
        }
    }
}

// ---------------------------------------------------------------------------
extern "C" void kernel_launch(void* const* d_in, const int* in_sizes, int n_in,
                              void* d_out, int out_size) {
    const float* inp = (const float*)d_in[0];   // (8,64,1024)
    const float* A   = (const float*)d_in[1];   // (256,256)
    const float* Bv  = (const float*)d_in[2];   // (256,)
    float* out = (float*)d_out;

    cudaFuncSetAttribute(main_mma_kernel,
                         cudaFuncAttributeMaxDynamicSharedMemorySize, SMEM_SZ);

    init_a_kernel<<<256, 256>>>(A);
    for (int d = 1; d <= 64; d <<= 1)
        pow_double_kernel<<<dim3(4, 4, d), 256>>>(d);

    v_kernel<<<128, 256>>>(Bv);
    qp2_kernel<<<dim3(4, 4), 256>>>();
    qp34_kernel<<<dim3(4, 4, 2), 256>>>();
    qp567_kernel<<<dim3(4, 4, 3), 256>>>();
    b_limbs_kernel<<<128 * NCHUNK, 256>>>();
    s_kernel<<<dim3(512, 8), 256>>>(inp);
    combine_all_kernel<<<dim3(4, 8, 7), 256>>>();
    a_limbs_kernel<<<32 * NCHUNK, 256>>>(inp);

    main_mma_kernel<<<dim3(128, 32), 512, SMEM_SZ>>>(out);
}

// round 8
// speedup vs baseline: 1.3092x; 1.3092x over previous
#include <cuda_runtime.h>
#include <cuda_fp16.h>
#include <cstdint>

// ---------------------------------------------------------------------------
// HiPPO-LegT: chunked convolution + one big GEMM.
// Main GEMM on mma.sync fp16 SINGLE limb (Ah*Bh, fp32 acc) + fine causal skip.
//
//  out[l, r, n] = sum_{k<=l} (A^{l-k} B)[n] * f[r, k]   (r = b*64+m, R=512)
//  Chunk T=128, C=8, v_j = A^j B:
//    out(i*T+t) = sum_{k<=t} v_{t-k} f[r,iT+k] + A^{t+1} h_{i-1}
//  One GEMM: Out(4096 x 32768) = X(4096 x 384) @ Kmat(384 x 32768)
// ---------------------------------------------------------------------------

#define N_ST   256
#define T_CH   128
#define MAT    65536
#define NCHUNK 6
#define AB_BLK 16384              // bytes: 128 rows x 64 k fp16 (swizzled)
#define BB_BLK 32768              // bytes: 256 rows x 64 k fp16 (swizzled)

// main mma kernel smem: per stage [Ah 16K][B 32K], 3 stages
#define ST_B   16384
#define ST_SZ  49152
#define NSTG   3
#define SMEM_SZ (NSTG * ST_SZ)

// ---- device scratch ----
__device__ __align__(256) float g_Apow[129 * MAT];     // A^1..A^128 at 1..128
__device__ __align__(256) float g_V[T_CH * N_ST];      // v_j = A^j B
__device__ __align__(256) float g_Qp[8 * MAT];         // (A^128)^p, p=2..7
__device__ __align__(256) float g_S[8 * 512 * N_ST];
__device__ __align__(256) float g_H[8 * 512 * N_ST];
__device__ __align__(256) __half g_Ah[(size_t)32 * NCHUNK * 8192];
__device__ __align__(256) __half g_Bh[(size_t)128 * NCHUNK * 16384];

// ---------------------------------------------------------------------------
__device__ __forceinline__ uint32_t smem_u32(const void* p) {
    uint32_t a;
    asm("{ .reg .u64 t; cvta.to.shared.u64 t, %1; cvt.u32.u64 %0, t; }" : "=r"(a) : "l"(p));
    return a;
}
__device__ __forceinline__ void cp16(uint32_t s, const void* g) {
    asm volatile("cp.async.cg.shared.global [%0], [%1], 16;" :: "r"(s), "l"(g));
}
#define CP_COMMIT() asm volatile("cp.async.commit_group;" ::: "memory")
#define CP_WAIT(n)  asm volatile("cp.async.wait_group %0;" :: "n"(n) : "memory")

__device__ __forceinline__ void ldm4(uint32_t* r, uint32_t addr) {
    asm volatile("ldmatrix.sync.aligned.m8n8.x4.shared.b16 {%0,%1,%2,%3}, [%4];"
                 : "=r"(r[0]), "=r"(r[1]), "=r"(r[2]), "=r"(r[3]) : "r"(addr));
}
__device__ __forceinline__ void mma16816(float* d, const uint32_t* a,
                                         uint32_t b0, uint32_t b1) {
    asm volatile(
        "mma.sync.aligned.m16n8k16.row.col.f32.f16.f16.f32 "
        "{%0,%1,%2,%3}, {%4,%5,%6,%7}, {%8,%9}, {%0,%1,%2,%3};"
        : "+f"(d[0]), "+f"(d[1]), "+f"(d[2]), "+f"(d[3])
        : "r"(a[0]), "r"(a[1]), "r"(a[2]), "r"(a[3]), "r"(b0), "r"(b1));
}

__device__ __forceinline__ uint32_t swz(uint32_t off) { return off ^ ((off >> 3) & 0x70); }

__device__ __forceinline__ unsigned short hbits(float x) {
    __half h = __float2half_rn(x);
    return *reinterpret_cast<unsigned short*>(&h);
}

// ---------------------------------------------------------------------------
// prologue (fp32 SIMT) — exact structure that passed rounds 4 & 7
// ---------------------------------------------------------------------------
__global__ void init_a_kernel(const float* __restrict__ A) {
    int idx = blockIdx.x * blockDim.x + threadIdx.x;
    if (idx < MAT) g_Apow[MAT + idx] = A[idx];
}

__device__ __forceinline__ void gemm64_body(const float* __restrict__ Am,
                                            const float* __restrict__ Bm,
                                            float* __restrict__ Cm,
                                            const float* __restrict__ bias) {
    __shared__ float As[16][64];
    __shared__ float Bs[16][64];
    const int brow = blockIdx.y * 64;
    const int bcol = blockIdx.x * 64;
    const int tid = threadIdx.x;
    const int tr = tid >> 4, tc = tid & 15;
    const int alr = tid >> 2, alc = (tid & 3) * 4;
    const int blr = tid >> 4, blc = (tid & 15) * 4;
    float acc[4][4] = {};
    for (int k0 = 0; k0 < 256; k0 += 16) {
        float4 a4 = *(const float4*)&Am[(brow + alr) * 256 + k0 + alc];
        As[alc + 0][alr] = a4.x; As[alc + 1][alr] = a4.y;
        As[alc + 2][alr] = a4.z; As[alc + 3][alr] = a4.w;
        float4 b4 = *(const float4*)&Bm[(k0 + blr) * 256 + bcol + blc];
        *(float4*)&Bs[blr][blc] = b4;
        __syncthreads();
#pragma unroll
        for (int k = 0; k < 16; k++) {
            float av[4], bv[4];
            *(float4*)&av[0] = *(const float4*)&As[k][tr * 4];
            *(float4*)&bv[0] = *(const float4*)&Bs[k][tc * 4];
#pragma unroll
            for (int ii = 0; ii < 4; ii++)
#pragma unroll
                for (int jj = 0; jj < 4; jj++)
                    acc[ii][jj] += av[ii] * bv[jj];
        }
        __syncthreads();
    }
#pragma unroll
    for (int ii = 0; ii < 4; ii++) {
        int rr = brow + tr * 4 + ii;
        int cc = bcol + tc * 4;
        float4 v;
        v.x = acc[ii][0]; v.y = acc[ii][1]; v.z = acc[ii][2]; v.w = acc[ii][3];
        if (bias) {
            float4 b = *(const float4*)&bias[rr * 256 + cc];
            v.x += b.x; v.y += b.y; v.z += b.z; v.w += b.w;
        }
        *(float4*)&Cm[rr * 256 + cc] = v;
    }
}

__global__ void pow_double_kernel(int d) {
    int j = blockIdx.z + 1;
    gemm64_body(g_Apow + (size_t)d * MAT, g_Apow + (size_t)j * MAT,
                g_Apow + (size_t)(d + j) * MAT, nullptr);
}

// Qp chain: Qp[p] = (A^128)^p
__global__ void qp2_kernel() {
    gemm64_body(g_Apow + (size_t)128 * MAT, g_Apow + (size_t)128 * MAT,
                g_Qp + (size_t)2 * MAT, nullptr);
}
__global__ void qp34_kernel() {
    if (blockIdx.z == 0)
        gemm64_body(g_Qp + (size_t)2 * MAT, g_Apow + (size_t)128 * MAT,
                    g_Qp + (size_t)3 * MAT, nullptr);
    else
        gemm64_body(g_Qp + (size_t)2 * MAT, g_Qp + (size_t)2 * MAT,
                    g_Qp + (size_t)4 * MAT, nullptr);
}
__global__ void qp567_kernel() {
    const float* rhs = (blockIdx.z == 0) ? g_Apow + (size_t)128 * MAT
                                         : g_Qp + (size_t)(blockIdx.z + 1) * MAT;
    gemm64_body(g_Qp + (size_t)4 * MAT, rhs,
                g_Qp + (size_t)(5 + blockIdx.z) * MAT, nullptr);
}

__global__ void v_kernel(const float* __restrict__ Bv) {
    __shared__ float bs[256];
    int j = blockIdx.x, n = threadIdx.x;
    bs[n] = Bv[n];
    __syncthreads();
    if (j == 0) { g_V[n] = bs[n]; return; }
    const float* Am = g_Apow + (size_t)j * MAT;
    float s = 0.f;
#pragma unroll 8
    for (int m = 0; m < 256; m++) s += Am[n * 256 + m] * bs[m];
    g_V[j * 256 + n] = s;
}

__global__ void s_kernel(const float* __restrict__ inp) {
    __shared__ float fs[128];
    int r = blockIdx.x, i = blockIdx.y, n = threadIdx.x;
    if (n < 128) fs[n] = inp[r * 1024 + i * T_CH + n];
    __syncthreads();
    float s = 0.f;
#pragma unroll 4
    for (int k = 0; k < 128; k++)
        s += g_V[(127 - k) * 256 + n] * fs[k];
    g_S[(i * 512 + r) * 256 + n] = s;
    if (i == 0) g_H[r * 256 + n] = s;
}

// H[i] = S[i] + sum_{j<i} S[j] * Qp[i-j]^T     (one parallel launch, i=1..7)
__global__ void combine_all_kernel() {
    __shared__ float As[16][64];
    __shared__ float Bs[16][64];
    const int i = blockIdx.z + 1;
    const int brow = blockIdx.y * 64;
    const int bcol = blockIdx.x * 64;
    const int tid = threadIdx.x;
    const int tr = tid >> 4, tc = tid & 15;
    const int alr = tid >> 2, alc = (tid & 3) * 4;
    const int bc = tid >> 2, bk = (tid & 3) * 4;
    float acc[4][4] = {};
    for (int j = 0; j < i; j++) {
        const int p = i - j;
        const float* Qp = (p == 1) ? g_Apow + (size_t)128 * MAT
                                   : g_Qp + (size_t)p * MAT;
        const float* Sj = g_S + (size_t)j * (512 * 256);
        for (int k0 = 0; k0 < 256; k0 += 16) {
            float4 a4 = *(const float4*)&Sj[(brow + alr) * 256 + k0 + alc];
            As[alc + 0][alr] = a4.x; As[alc + 1][alr] = a4.y;
            As[alc + 2][alr] = a4.z; As[alc + 3][alr] = a4.w;
            float4 q4 = *(const float4*)&Qp[(size_t)(bcol + bc) * 256 + k0 + bk];
            Bs[bk + 0][bc] = q4.x; Bs[bk + 1][bc] = q4.y;
            Bs[bk + 2][bc] = q4.z; Bs[bk + 3][bc] = q4.w;
            __syncthreads();
#pragma unroll
            for (int k = 0; k < 16; k++) {
                float av[4], bv[4];
                *(float4*)&av[0] = *(const float4*)&As[k][tr * 4];
                *(float4*)&bv[0] = *(const float4*)&Bs[k][tc * 4];
#pragma unroll
                for (int ii = 0; ii < 4; ii++)
#pragma unroll
                    for (int jj = 0; jj < 4; jj++)
                        acc[ii][jj] += av[ii] * bv[jj];
            }
            __syncthreads();
        }
    }
    float* Hout = g_H + (size_t)i * (512 * 256);
    const float* Si = g_S + (size_t)i * (512 * 256);
#pragma unroll
    for (int ii = 0; ii < 4; ii++) {
        int rr = brow + tr * 4 + ii;
        int cc = bcol + tc * 4;
        float4 b = *(const float4*)&Si[rr * 256 + cc];
        float4 v;
        v.x = acc[ii][0] + b.x; v.y = acc[ii][1] + b.y;
        v.z = acc[ii][2] + b.z; v.w = acc[ii][3] + b.w;
        *(float4*)&Hout[rr * 256 + cc] = v;
    }
}

// ---------------------------------------------------------------------------
// packers (fp16 single limb), SW128-swizzled, exact smem image.
// ---------------------------------------------------------------------------
__global__ void b_limbs_kernel() {
    const int blk = blockIdx.x;            // t*6 + kc
    const int t = blk / NCHUNK, kc = blk % NCHUNK;
    const int tid = threadIdx.x;
    const int kk0 = (tid & 15) * 4;
    char* dh = (char*)g_Bh + (size_t)blk * BB_BLK;
    for (int it = 0; it < 16; it++) {
        int n = it * 16 + (tid >> 4);
        float v[4];
        if (kc < 2) {
            int k0 = kc * 64 + kk0;
#pragma unroll
            for (int q = 0; q < 4; q++) {
                int k = k0 + q;
                v[q] = (k <= t) ? g_V[(t - k) * 256 + n] : 0.f;
            }
        } else {
            int m0 = kc * 64 + kk0 - 128;
            float4 a4 = *(const float4*)&g_Apow[(size_t)(t + 1) * MAT + n * 256 + m0];
            v[0] = a4.x; v[1] = a4.y; v[2] = a4.z; v[3] = a4.w;
        }
        uint2 ph;
        ph.x = (uint32_t)hbits(v[0]) | ((uint32_t)hbits(v[1]) << 16);
        ph.y = (uint32_t)hbits(v[2]) | ((uint32_t)hbits(v[3]) << 16);
        uint32_t off = swz((uint32_t)(n * 128 + kk0 * 2));
        *(uint2*)(dh + off) = ph;
    }
}

__global__ void a_limbs_kernel(const float* __restrict__ inp) {
    const int blk = blockIdx.x;            // rt*6 + kc
    const int rt = blk / NCHUNK, kc = blk % NCHUNK;
    const int i = rt >> 2;
    const int tid = threadIdx.x;
    const int kk0 = (tid & 15) * 4;
    char* dh = (char*)g_Ah + (size_t)blk * AB_BLK;
    for (int it = 0; it < 8; it++) {
        int row = it * 16 + (tid >> 4);
        int r = (rt & 3) * 128 + row;
        float v[4];
        if (kc < 2) {
            float4 f4 = *(const float4*)&inp[r * 1024 + i * 128 + kc * 64 + kk0];
            v[0] = f4.x; v[1] = f4.y; v[2] = f4.z; v[3] = f4.w;
        } else if (i == 0) {
            v[0] = v[1] = v[2] = v[3] = 0.f;
        } else {
            float4 f4 = *(const float4*)&g_H[(size_t)((i - 1) * 512 + r) * 256 +
                                             (kc - 2) * 64 + kk0];
            v[0] = f4.x; v[1] = f4.y; v[2] = f4.z; v[3] = f4.w;
        }
        uint2 ph;
        ph.x = (uint32_t)hbits(v[0]) | ((uint32_t)hbits(v[1]) << 16);
        ph.y = (uint32_t)hbits(v[2]) | ((uint32_t)hbits(v[3]) << 16);
        uint32_t off = swz((uint32_t)(row * 128 + kk0 * 2));
        *(uint2*)(dh + off) = ph;
    }
}

// ---------------------------------------------------------------------------
// Main GEMM: fp16 SINGLE-limb mma.sync. CTA = 128x256 out tile, 512 threads
// (16 warps, 32x64 warp tiles), 3-stage cp.async pipeline. Causal skip at
// chunk level (kc=1 for t<64) AND k16-step level inside W-chunks.
// grid (128 t-tiles, 32 row tiles).
// ---------------------------------------------------------------------------
__global__ __launch_bounds__(512, 1) void main_mma_kernel(float* __restrict__ out) {
    extern __shared__ char smem[];
    const uint32_t sb = smem_u32(smem);
    const int tid = threadIdx.x;
    const int wid = tid >> 5;
    const int lane = tid & 31;
    const int t = blockIdx.x;           // col tile = t (full 256 cols)
    const int by = blockIdx.y;          // row tile

    const int m0w = (wid & 3) * 32;
    const int n0w = (wid >> 2) * 64;

    // chunk list: skip kc=1 when t<64 (all-zero causal block)
    int clist[6] = {0, 1, 2, 3, 4, 5};
    int nch = 6;
    if (t < 64) { clist[1] = 2; clist[2] = 3; clist[3] = 4; clist[4] = 5; nch = 5; }

    // per-chunk useful k16-step counts (causal fine skip in W-part)
    const int nks_c0 = min(4, (t >> 4) + 1);
    const int nks_c1 = (t < 64) ? 0 : min(4, ((t - 64) >> 4) + 1);

    const char* Asrc = (const char*)g_Ah + (size_t)by * NCHUNK * AB_BLK;
    const char* Bsrc = (const char*)g_Bh + (size_t)t * NCHUNK * BB_BLK;

    const uint32_t cpo = (uint32_t)tid * 16;   // < 8192

    uint32_t aoff[2][4];
    uint32_t boff[4][4];
    {
        const uint32_t arow = (uint32_t)(m0w + (lane & 15)) * 128;
        const uint32_t khalf = (uint32_t)(lane >> 4) * 16;
#pragma unroll
        for (int mt = 0; mt < 2; mt++)
#pragma unroll
            for (int ks = 0; ks < 4; ks++)
                aoff[mt][ks] = swz(arow + (uint32_t)mt * 2048 + khalf + ks * 32);
        const uint32_t brow = (uint32_t)(n0w + (lane & 15)) * 128;
#pragma unroll
        for (int ng = 0; ng < 4; ng++)
#pragma unroll
            for (int ks = 0; ks < 4; ks++)
                boff[ng][ks] = swz(brow + (uint32_t)ng * 2048 + khalf + ks * 32);
    }

    float acc[2][8][4];
#pragma unroll
    for (int mt = 0; mt < 2; mt++)
#pragma unroll
        for (int nt = 0; nt < 8; nt++)
#pragma unroll
            for (int q = 0; q < 4; q++) acc[mt][nt][q] = 0.f;

#define LOAD_STAGE(kc, st)                                                      \
    do {                                                                        \
        uint32_t s0 = sb + (uint32_t)(st) * ST_SZ;                              \
        const char* ga = Asrc + (size_t)(kc) * AB_BLK;                          \
        const char* gc = Bsrc + (size_t)(kc) * BB_BLK;                          \
        cp16(s0 + cpo, ga + cpo);                                               \
        cp16(s0 + 8192 + cpo, ga + 8192 + cpo);                                 \
        _Pragma("unroll")                                                       \
        for (int q = 0; q < 4; q++)                                             \
            cp16(s0 + ST_B + q * 8192 + cpo, gc + q * 8192 + cpo);              \
        CP_COMMIT();                                                            \
    } while (0)

    LOAD_STAGE(clist[0], 0);
    LOAD_STAGE(clist[1], 1);

    for (int j = 0; j < nch; j++) {
        if (j + NSTG - 1 < nch) {
            LOAD_STAGE(clist[j + NSTG - 1], (j + NSTG - 1) % NSTG);
            CP_WAIT(2);
        } else if (j == nch - 2) {
            CP_WAIT(1);
        } else {
            CP_WAIT(0);
        }
        __syncthreads();
        const uint32_t st = sb + (uint32_t)(j % NSTG) * ST_SZ;
        const int kc = clist[j];
        const int nks = (kc == 0) ? nks_c0 : ((kc == 1) ? nks_c1 : 4);
#pragma unroll
        for (int ks = 0; ks < 4; ks++) {
            if (ks >= nks) break;
            uint32_t ah[2][4];
            ldm4(ah[0], st + aoff[0][ks]);
            ldm4(ah[1], st + aoff[1][ks]);
#pragma unroll
            for (int ng = 0; ng < 4; ng++) {
                uint32_t bh[4];
                ldm4(bh, st + ST_B + boff[ng][ks]);
#pragma unroll
                for (int mt = 0; mt < 2; mt++) {
                    mma16816(acc[mt][2 * ng + 0], ah[mt], bh[0], bh[2]);
                    mma16816(acc[mt][2 * ng + 1], ah[mt], bh[1], bh[3]);
                }
            }
        }
        __syncthreads();
    }
#undef LOAD_STAGE

    // epilogue: out[(i*128 + t)*131072 + r*256 + n]
    const int i_ch = by >> 2;
    float* ob = out + (size_t)(i_ch * 128 + t) * 131072;
    const int rbase = (by & 3) * 128 + m0w + (lane >> 2);
    const int cbase = n0w + (lane & 3) * 2;
#pragma unroll
    for (int mt = 0; mt < 2; mt++) {
        const int r0 = rbase + mt * 16;
#pragma unroll
        for (int nt = 0; nt < 8; nt++) {
            const int c = cbase + nt * 8;
            float2 v0 = make_float2(acc[mt][nt][0], acc[mt][nt][1]);
            float2 v1 = make_float2(acc[mt][nt][2], acc[mt][nt][3]);
            __stcs((float2*)(ob + (size_t)r0 * 256 + c), v0);
            __stcs((float2*)(ob + (size_t)(r0 + 8) * 256 + c), v1);
        }
    }
}

// ---------------------------------------------------------------------------
extern "C" void kernel_launch(void* const* d_in, const int* in_sizes, int n_in,
                              void* d_out, int out_size) {
    const float* inp = (const float*)d_in[0];   // (8,64,1024)
    const float* A   = (const float*)d_in[1];   // (256,256)
    const float* Bv  = (const float*)d_in[2];   // (256,)
    float* out = (float*)d_out;

    cudaFuncSetAttribute(main_mma_kernel,
                         cudaFuncAttributeMaxDynamicSharedMemorySize, SMEM_SZ);

    init_a_kernel<<<256, 256>>>(A);
    for (int d = 1; d <= 64; d <<= 1)
        pow_double_kernel<<<dim3(4, 4, d), 256>>>(d);

    v_kernel<<<128, 256>>>(Bv);
    qp2_kernel<<<dim3(4, 4), 256>>>();
    qp34_kernel<<<dim3(4, 4, 2), 256>>>();
    qp567_kernel<<<dim3(4, 4, 3), 256>>>();
    b_limbs_kernel<<<128 * NCHUNK, 256>>>();
    s_kernel<<<dim3(512, 8), 256>>>(inp);
    combine_all_kernel<<<dim3(4, 8, 7), 256>>>();
    a_limbs_kernel<<<32 * NCHUNK, 256>>>(inp);

    main_mma_kernel<<<dim3(128, 32), 512, SMEM_SZ>>>(out);
}

// round 9
// speedup vs baseline: 1.3427x; 1.0256x over previous
#include <cuda_runtime.h>
#include <cuda_fp16.h>
#include <cstdint>

// ---------------------------------------------------------------------------
// HiPPO-LegT: chunked convolution + one big GEMM.
// Main GEMM on mma.sync fp16 single limb (Ah*Bh, fp32 acc) + causal skips.
// Prologue: 32x32-tile fp32 GEMMs (short CTA critical path) + Horner combine.
//
//  out[l, r, n] = sum_{k<=l} (A^{l-k} B)[n] * f[r, k]   (r = b*64+m, R=512)
//  Chunk T=128, C=8, v_j = A^j B:
//    out(i*T+t) = sum_{k<=t} v_{t-k} f[r,iT+k] + A^{t+1} h_{i-1}
//  One GEMM: Out(4096 x 32768) = X(4096 x 384) @ Kmat(384 x 32768)
// ---------------------------------------------------------------------------

#define N_ST   256
#define T_CH   128
#define MAT    65536
#define NCHUNK 6
#define AB_BLK 16384              // bytes: 128 rows x 64 k fp16 (swizzled)
#define BB_BLK 32768              // bytes: 256 rows x 64 k fp16 (swizzled)

// main mma kernel smem: per stage [Ah 16K][B 32K], 3 stages
#define ST_B   16384
#define ST_SZ  49152
#define NSTG   3
#define SMEM_SZ (NSTG * ST_SZ)

// ---- device scratch ----
__device__ __align__(256) float g_Apow[129 * MAT];     // A^1..A^128 at 1..128
__device__ __align__(256) float g_V[T_CH * N_ST];      // v_j = A^j B
__device__ __align__(256) float g_S[8 * 512 * N_ST];
__device__ __align__(256) float g_H[8 * 512 * N_ST];
__device__ __align__(256) __half g_Ah[(size_t)32 * NCHUNK * 8192];
__device__ __align__(256) __half g_Bh[(size_t)128 * NCHUNK * 16384];

// ---------------------------------------------------------------------------
__device__ __forceinline__ uint32_t smem_u32(const void* p) {
    uint32_t a;
    asm("{ .reg .u64 t; cvta.to.shared.u64 t, %1; cvt.u32.u64 %0, t; }" : "=r"(a) : "l"(p));
    return a;
}
__device__ __forceinline__ void cp16(uint32_t s, const void* g) {
    asm volatile("cp.async.cg.shared.global [%0], [%1], 16;" :: "r"(s), "l"(g));
}
#define CP_COMMIT() asm volatile("cp.async.commit_group;" ::: "memory")
#define CP_WAIT(n)  asm volatile("cp.async.wait_group %0;" :: "n"(n) : "memory")

__device__ __forceinline__ void ldm4(uint32_t* r, uint32_t addr) {
    asm volatile("ldmatrix.sync.aligned.m8n8.x4.shared.b16 {%0,%1,%2,%3}, [%4];"
                 : "=r"(r[0]), "=r"(r[1]), "=r"(r[2]), "=r"(r[3]) : "r"(addr));
}
__device__ __forceinline__ void mma16816(float* d, const uint32_t* a,
                                         uint32_t b0, uint32_t b1) {
    asm volatile(
        "mma.sync.aligned.m16n8k16.row.col.f32.f16.f16.f32 "
        "{%0,%1,%2,%3}, {%4,%5,%6,%7}, {%8,%9}, {%0,%1,%2,%3};"
        : "+f"(d[0]), "+f"(d[1]), "+f"(d[2]), "+f"(d[3])
        : "r"(a[0]), "r"(a[1]), "r"(a[2]), "r"(a[3]), "r"(b0), "r"(b1));
}

__device__ __forceinline__ uint32_t swz(uint32_t off) { return off ^ ((off >> 3) & 0x70); }

__device__ __forceinline__ unsigned short hbits(float x) {
    __half h = __float2half_rn(x);
    return *reinterpret_cast<unsigned short*>(&h);
}

// ---------------------------------------------------------------------------
// prologue: 32x32-tile fp32 GEMM bodies (short per-CTA critical path).
// All matrices row-major 256x256 (ld=256); H/S tiles are 512x256 (ld=256).
// ---------------------------------------------------------------------------
__global__ void init_a_kernel(const float* __restrict__ A) {
    int idx = blockIdx.x * blockDim.x + threadIdx.x;
    if (idx < MAT) g_Apow[MAT + idx] = A[idx];
}

// C[brow+r][bcol+c] = sum_k Am[(brow+r)*256+k] * Bm[(k)*256 + bcol+c]
// 256 threads, 2x2 outputs per thread.
__device__ __forceinline__ void gemm32_nn(const float* __restrict__ Am,
                                          const float* __restrict__ Bm,
                                          float* __restrict__ Cm,
                                          int brow, int bcol) {
    __shared__ float As[16][33];
    __shared__ float Bs[16][33];
    const int tid = threadIdx.x;
    const int ty = tid >> 4, tx = tid & 15;
    const int ar = tid >> 3;            // 0..31
    const int ak = (tid & 7) * 2;       // 0..14
    const int bk = tid >> 4;            // 0..15
    const int bc = (tid & 15) * 2;      // 0..30
    float acc[2][2] = {};
    for (int k0 = 0; k0 < 256; k0 += 16) {
        float2 a2 = *(const float2*)&Am[(size_t)(brow + ar) * 256 + k0 + ak];
        As[ak][ar] = a2.x; As[ak + 1][ar] = a2.y;
        float2 b2 = *(const float2*)&Bm[(size_t)(k0 + bk) * 256 + bcol + bc];
        Bs[bk][bc] = b2.x; Bs[bk][bc + 1] = b2.y;
        __syncthreads();
#pragma unroll
        for (int k = 0; k < 16; k++) {
            float a0 = As[k][ty * 2], a1 = As[k][ty * 2 + 1];
            float b0 = Bs[k][tx * 2], b1 = Bs[k][tx * 2 + 1];
            acc[0][0] += a0 * b0; acc[0][1] += a0 * b1;
            acc[1][0] += a1 * b0; acc[1][1] += a1 * b1;
        }
        __syncthreads();
    }
#pragma unroll
    for (int ii = 0; ii < 2; ii++) {
        float2 v = make_float2(acc[ii][0], acc[ii][1]);
        *(float2*)&Cm[(size_t)(brow + ty * 2 + ii) * 256 + bcol + tx * 2] = v;
    }
}

// C[brow+r][bcol+c] = sum_k Am[(brow+r)*256+k] * Bt[(bcol+c)*256+k]  (+ bias)
__device__ __forceinline__ void gemm32_ntr(const float* __restrict__ Am,
                                           const float* __restrict__ Bt,
                                           float* __restrict__ Cm,
                                           const float* __restrict__ bias,
                                           int brow, int bcol) {
    __shared__ float As[16][33];
    __shared__ float Bs[16][33];
    const int tid = threadIdx.x;
    const int ty = tid >> 4, tx = tid & 15;
    const int ar = tid >> 3;            // 0..31
    const int ak = (tid & 7) * 2;       // 0..14
    float acc[2][2] = {};
    for (int k0 = 0; k0 < 256; k0 += 16) {
        float2 a2 = *(const float2*)&Am[(size_t)(brow + ar) * 256 + k0 + ak];
        As[ak][ar] = a2.x; As[ak + 1][ar] = a2.y;
        float2 b2 = *(const float2*)&Bt[(size_t)(bcol + ar) * 256 + k0 + ak];
        Bs[ak][ar] = b2.x; Bs[ak + 1][ar] = b2.y;
        __syncthreads();
#pragma unroll
        for (int k = 0; k < 16; k++) {
            float a0 = As[k][ty * 2], a1 = As[k][ty * 2 + 1];
            float b0 = Bs[k][tx * 2], b1 = Bs[k][tx * 2 + 1];
            acc[0][0] += a0 * b0; acc[0][1] += a0 * b1;
            acc[1][0] += a1 * b0; acc[1][1] += a1 * b1;
        }
        __syncthreads();
    }
#pragma unroll
    for (int ii = 0; ii < 2; ii++) {
        const size_t off = (size_t)(brow + ty * 2 + ii) * 256 + bcol + tx * 2;
        float2 b = *(const float2*)&bias[off];
        float2 v = make_float2(acc[ii][0] + b.x, acc[ii][1] + b.y);
        *(float2*)&Cm[off] = v;
    }
}

// A^{d+j} = A^d @ A^j for j = 1..d   grid (8, 8, d)
__global__ void pow_double_kernel(int d) {
    int j = blockIdx.z + 1;
    gemm32_nn(g_Apow + (size_t)d * MAT, g_Apow + (size_t)j * MAT,
              g_Apow + (size_t)(d + j) * MAT,
              blockIdx.y * 32, blockIdx.x * 32);
}

// Horner: H[i+1] = H[i] @ (A^128)^T + S[i+1]   grid (8, 16)
__global__ void combine_step_kernel(int i) {
    gemm32_ntr(g_H + (size_t)i * (512 * 256),
               g_Apow + (size_t)128 * MAT,
               g_H + (size_t)(i + 1) * (512 * 256),
               g_S + (size_t)(i + 1) * (512 * 256),
               blockIdx.y * 32, blockIdx.x * 32);
}

__global__ void v_kernel(const float* __restrict__ Bv) {
    __shared__ float bs[256];
    int j = blockIdx.x, n = threadIdx.x;
    bs[n] = Bv[n];
    __syncthreads();
    if (j == 0) { g_V[n] = bs[n]; return; }
    const float* Am = g_Apow + (size_t)j * MAT;
    float s = 0.f;
#pragma unroll 8
    for (int m = 0; m < 256; m++) s += Am[n * 256 + m] * bs[m];
    g_V[j * 256 + n] = s;
}

__global__ void s_kernel(const float* __restrict__ inp) {
    __shared__ float fs[128];
    int r = blockIdx.x, i = blockIdx.y, n = threadIdx.x;
    if (n < 128) fs[n] = inp[r * 1024 + i * T_CH + n];
    __syncthreads();
    float s = 0.f;
#pragma unroll 4
    for (int k = 0; k < 128; k++)
        s += g_V[(127 - k) * 256 + n] * fs[k];
    g_S[(i * 512 + r) * 256 + n] = s;
    if (i == 0) g_H[r * 256 + n] = s;   // H[0] = S[0]
}

// ---------------------------------------------------------------------------
// packers (fp16 single limb), SW128-swizzled, exact smem image.
// ---------------------------------------------------------------------------
__global__ void b_limbs_kernel() {
    const int blk = blockIdx.x;            // t*6 + kc
    const int t = blk / NCHUNK, kc = blk % NCHUNK;
    const int tid = threadIdx.x;
    const int kk0 = (tid & 15) * 4;
    char* dh = (char*)g_Bh + (size_t)blk * BB_BLK;
    for (int it = 0; it < 16; it++) {
        int n = it * 16 + (tid >> 4);
        float v[4];
        if (kc < 2) {
            int k0 = kc * 64 + kk0;
#pragma unroll
            for (int q = 0; q < 4; q++) {
                int k = k0 + q;
                v[q] = (k <= t) ? g_V[(t - k) * 256 + n] : 0.f;
            }
        } else {
            int m0 = kc * 64 + kk0 - 128;
            float4 a4 = *(const float4*)&g_Apow[(size_t)(t + 1) * MAT + n * 256 + m0];
            v[0] = a4.x; v[1] = a4.y; v[2] = a4.z; v[3] = a4.w;
        }
        uint2 ph;
        ph.x = (uint32_t)hbits(v[0]) | ((uint32_t)hbits(v[1]) << 16);
        ph.y = (uint32_t)hbits(v[2]) | ((uint32_t)hbits(v[3]) << 16);
        uint32_t off = swz((uint32_t)(n * 128 + kk0 * 2));
        *(uint2*)(dh + off) = ph;
    }
}

__global__ void a_limbs_kernel(const float* __restrict__ inp) {
    const int blk = blockIdx.x;            // rt*6 + kc
    const int rt = blk / NCHUNK, kc = blk % NCHUNK;
    const int i = rt >> 2;
    const int tid = threadIdx.x;
    const int kk0 = (tid & 15) * 4;
    char* dh = (char*)g_Ah + (size_t)blk * AB_BLK;
    for (int it = 0; it < 8; it++) {
        int row = it * 16 + (tid >> 4);
        int r = (rt & 3) * 128 + row;
        float v[4];
        if (kc < 2) {
            float4 f4 = *(const float4*)&inp[r * 1024 + i * 128 + kc * 64 + kk0];
            v[0] = f4.x; v[1] = f4.y; v[2] = f4.z; v[3] = f4.w;
        } else if (i == 0) {
            v[0] = v[1] = v[2] = v[3] = 0.f;
        } else {
            float4 f4 = *(const float4*)&g_H[(size_t)((i - 1) * 512 + r) * 256 +
                                             (kc - 2) * 64 + kk0];
            v[0] = f4.x; v[1] = f4.y; v[2] = f4.z; v[3] = f4.w;
        }
        uint2 ph;
        ph.x = (uint32_t)hbits(v[0]) | ((uint32_t)hbits(v[1]) << 16);
        ph.y = (uint32_t)hbits(v[2]) | ((uint32_t)hbits(v[3]) << 16);
        uint32_t off = swz((uint32_t)(row * 128 + kk0 * 2));
        *(uint2*)(dh + off) = ph;
    }
}

// ---------------------------------------------------------------------------
// Main GEMM: fp16 SINGLE-limb mma.sync. CTA = 128x256 out tile, 512 threads
// (16 warps, 32x64 warp tiles), 3-stage cp.async pipeline. Causal skip at
// chunk level (kc=1 for t<64) AND k16-step level inside W-chunks.
// grid (128 t-tiles, 32 row tiles).     [unchanged from round 8 — passing]
// ---------------------------------------------------------------------------
__global__ __launch_bounds__(512, 1) void main_mma_kernel(float* __restrict__ out) {
    extern __shared__ char smem[];
    const uint32_t sb = smem_u32(smem);
    const int tid = threadIdx.x;
    const int wid = tid >> 5;
    const int lane = tid & 31;
    const int t = blockIdx.x;
    const int by = blockIdx.y;

    const int m0w = (wid & 3) * 32;
    const int n0w = (wid >> 2) * 64;

    int clist[6] = {0, 1, 2, 3, 4, 5};
    int nch = 6;
    if (t < 64) { clist[1] = 2; clist[2] = 3; clist[3] = 4; clist[4] = 5; nch = 5; }

    const int nks_c0 = min(4, (t >> 4) + 1);
    const int nks_c1 = (t < 64) ? 0 : min(4, ((t - 64) >> 4) + 1);

    const char* Asrc = (const char*)g_Ah + (size_t)by * NCHUNK * AB_BLK;
    const char* Bsrc = (const char*)g_Bh + (size_t)t * NCHUNK * BB_BLK;

    const uint32_t cpo = (uint32_t)tid * 16;

    uint32_t aoff[2][4];
    uint32_t boff[4][4];
    {
        const uint32_t arow = (uint32_t)(m0w + (lane & 15)) * 128;
        const uint32_t khalf = (uint32_t)(lane >> 4) * 16;
#pragma unroll
        for (int mt = 0; mt < 2; mt++)
#pragma unroll
            for (int ks = 0; ks < 4; ks++)
                aoff[mt][ks] = swz(arow + (uint32_t)mt * 2048 + khalf + ks * 32);
        const uint32_t brow = (uint32_t)(n0w + (lane & 15)) * 128;
#pragma unroll
        for (int ng = 0; ng < 4; ng++)
#pragma unroll
            for (int ks = 0; ks < 4; ks++)
                boff[ng][ks] = swz(brow + (uint32_t)ng * 2048 + khalf + ks * 32);
    }

    float acc[2][8][4];
#pragma unroll
    for (int mt = 0; mt < 2; mt++)
#pragma unroll
        for (int nt = 0; nt < 8; nt++)
#pragma unroll
            for (int q = 0; q < 4; q++) acc[mt][nt][q] = 0.f;

#define LOAD_STAGE(kc, st)                                                      \
    do {                                                                        \
        uint32_t s0 = sb + (uint32_t)(st) * ST_SZ;                              \
        const char* ga = Asrc + (size_t)(kc) * AB_BLK;                          \
        const char* gc = Bsrc + (size_t)(kc) * BB_BLK;                          \
        cp16(s0 + cpo, ga + cpo);                                               \
        cp16(s0 + 8192 + cpo, ga + 8192 + cpo);                                 \
        _Pragma("unroll")                                                       \
        for (int q = 0; q < 4; q++)                                             \
            cp16(s0 + ST_B + q * 8192 + cpo, gc + q * 8192 + cpo);              \
        CP_COMMIT();                                                            \
    } while (0)

    LOAD_STAGE(clist[0], 0);
    LOAD_STAGE(clist[1], 1);

    for (int j = 0; j < nch; j++) {
        if (j + NSTG - 1 < nch) {
            LOAD_STAGE(clist[j + NSTG - 1], (j + NSTG - 1) % NSTG);
            CP_WAIT(2);
        } else if (j == nch - 2) {
            CP_WAIT(1);
        } else {
            CP_WAIT(0);
        }
        __syncthreads();
        const uint32_t st = sb + (uint32_t)(j % NSTG) * ST_SZ;
        const int kc = clist[j];
        const int nks = (kc == 0) ? nks_c0 : ((kc == 1) ? nks_c1 : 4);
#pragma unroll
        for (int ks = 0; ks < 4; ks++) {
            if (ks >= nks) break;
            uint32_t ah[2][4];
            ldm4(ah[0], st + aoff[0][ks]);
            ldm4(ah[1], st + aoff[1][ks]);
#pragma unroll
            for (int ng = 0; ng < 4; ng++) {
                uint32_t bh[4];
                ldm4(bh, st + ST_B + boff[ng][ks]);
#pragma unroll
                for (int mt = 0; mt < 2; mt++) {
                    mma16816(acc[mt][2 * ng + 0], ah[mt], bh[0], bh[2]);
                    mma16816(acc[mt][2 * ng + 1], ah[mt], bh[1], bh[3]);
                }
            }
        }
        __syncthreads();
    }
#undef LOAD_STAGE

    const int i_ch = by >> 2;
    float* ob = out + (size_t)(i_ch * 128 + t) * 131072;
    const int rbase = (by & 3) * 128 + m0w + (lane >> 2);
    const int cbase = n0w + (lane & 3) * 2;
#pragma unroll
    for (int mt = 0; mt < 2; mt++) {
        const int r0 = rbase + mt * 16;
#pragma unroll
        for (int nt = 0; nt < 8; nt++) {
            const int c = cbase + nt * 8;
            float2 v0 = make_float2(acc[mt][nt][0], acc[mt][nt][1]);
            float2 v1 = make_float2(acc[mt][nt][2], acc[mt][nt][3]);
            __stcs((float2*)(ob + (size_t)r0 * 256 + c), v0);
            __stcs((float2*)(ob + (size_t)(r0 + 8) * 256 + c), v1);
        }
    }
}

// ---------------------------------------------------------------------------
extern "C" void kernel_launch(void* const* d_in, const int* in_sizes, int n_in,
                              void* d_out, int out_size) {
    const float* inp = (const float*)d_in[0];   // (8,64,1024)
    const float* A   = (const float*)d_in[1];   // (256,256)
    const float* Bv  = (const float*)d_in[2];   // (256,)
    float* out = (float*)d_out;

    cudaFuncSetAttribute(main_mma_kernel,
                         cudaFuncAttributeMaxDynamicSharedMemorySize, SMEM_SZ);

    init_a_kernel<<<256, 256>>>(A);
    for (int d = 1; d <= 64; d <<= 1)
        pow_double_kernel<<<dim3(8, 8, d), 256>>>(d);

    v_kernel<<<128, 256>>>(Bv);
    b_limbs_kernel<<<128 * NCHUNK, 256>>>();
    s_kernel<<<dim3(512, 8), 256>>>(inp);
    for (int i = 0; i < 7; i++)                 // H[1..7] via Horner
        combine_step_kernel<<<dim3(8, 16), 256>>>(i);
    a_limbs_kernel<<<32 * NCHUNK, 256>>>(inp);

    main_mma_kernel<<<dim3(128, 32), 512, SMEM_SZ>>>(out);
}

// round 10
// speedup vs baseline: 1.4022x; 1.0443x over previous
#include <cuda_runtime.h>
#include <cuda_fp16.h>
#include <cuda_bf16.h>
#include <cstdint>

// ---------------------------------------------------------------------------
// HiPPO-LegT: chunked convolution + one big GEMM.
// Main GEMM: mma.sync fp16 single limb (Ah*Bh, fp32 acc) + causal skips.
// Pow chain (A^1..A^128): tensor-core 3-limb bf16 (AhBh+AhBl+AlBh) — ~fp32
// accurate (4.4e-6/product), replaces 125us of fp32 FFMA with ~50us of HMMA.
// Combine: Horner H[i+1] = H[i] (A^128)^T + S[i+1] on 32x32 fp32 tiles.
// ---------------------------------------------------------------------------

#define N_ST   256
#define T_CH   128
#define MAT    65536
#define NCHUNK 6
#define AB_BLK 16384              // bytes: 128 rows x 64 k fp16 (swizzled)
#define BB_BLK 32768              // bytes: 256 rows x 64 k fp16 (swizzled)

// main mma kernel smem: per stage [Ah 16K][B 32K], 3 stages
#define ST_B   16384
#define ST_SZ  49152
#define NSTG   3
#define SMEM_SZ (NSTG * ST_SZ)

// pow mma kernel smem: [Ph 16K][Pl 16K][Rh 16K][Rl 16K]
#define PW_PL  16384
#define PW_RH  32768
#define PW_RL  49152
#define PW_SMEM 65536

// ---- device scratch ----
__device__ __align__(256) float g_Apow[129 * MAT];     // A^1..A^128 at 1..128
__device__ __align__(256) float g_V[T_CH * N_ST];      // v_j = A^j B
__device__ __align__(256) float g_S[8 * 512 * N_ST];
__device__ __align__(256) float g_H[8 * 512 * N_ST];
__device__ __align__(256) __half g_Ah[(size_t)32 * NCHUNK * 8192];
__device__ __align__(256) __half g_Bh[(size_t)128 * NCHUNK * 16384];

// ---------------------------------------------------------------------------
__device__ __forceinline__ uint32_t smem_u32(const void* p) {
    uint32_t a;
    asm("{ .reg .u64 t; cvta.to.shared.u64 t, %1; cvt.u32.u64 %0, t; }" : "=r"(a) : "l"(p));
    return a;
}
__device__ __forceinline__ void cp16(uint32_t s, const void* g) {
    asm volatile("cp.async.cg.shared.global [%0], [%1], 16;" :: "r"(s), "l"(g));
}
#define CP_COMMIT() asm volatile("cp.async.commit_group;" ::: "memory")
#define CP_WAIT(n)  asm volatile("cp.async.wait_group %0;" :: "n"(n) : "memory")

__device__ __forceinline__ void ldm4(uint32_t* r, uint32_t addr) {
    asm volatile("ldmatrix.sync.aligned.m8n8.x4.shared.b16 {%0,%1,%2,%3}, [%4];"
                 : "=r"(r[0]), "=r"(r[1]), "=r"(r[2]), "=r"(r[3]) : "r"(addr));
}
__device__ __forceinline__ void mma16816(float* d, const uint32_t* a,
                                         uint32_t b0, uint32_t b1) {
    asm volatile(
        "mma.sync.aligned.m16n8k16.row.col.f32.f16.f16.f32 "
        "{%0,%1,%2,%3}, {%4,%5,%6,%7}, {%8,%9}, {%0,%1,%2,%3};"
        : "+f"(d[0]), "+f"(d[1]), "+f"(d[2]), "+f"(d[3])
        : "r"(a[0]), "r"(a[1]), "r"(a[2]), "r"(a[3]), "r"(b0), "r"(b1));
}
__device__ __forceinline__ void mmabf(float* d, const uint32_t* a,
                                      uint32_t b0, uint32_t b1) {
    asm volatile(
        "mma.sync.aligned.m16n8k16.row.col.f32.bf16.bf16.f32 "
        "{%0,%1,%2,%3}, {%4,%5,%6,%7}, {%8,%9}, {%0,%1,%2,%3};"
        : "+f"(d[0]), "+f"(d[1]), "+f"(d[2]), "+f"(d[3])
        : "r"(a[0]), "r"(a[1]), "r"(a[2]), "r"(a[3]), "r"(b0), "r"(b1));
}

__device__ __forceinline__ uint32_t swz(uint32_t off) { return off ^ ((off >> 3) & 0x70); }

__device__ __forceinline__ unsigned short hbits(float x) {
    __half h = __float2half_rn(x);
    return *reinterpret_cast<unsigned short*>(&h);
}
__device__ __forceinline__ unsigned short bfb(__nv_bfloat16 b) {
    return *reinterpret_cast<unsigned short*>(&b);
}

// ---------------------------------------------------------------------------
__global__ void init_a_kernel(const float* __restrict__ A) {
    int idx = blockIdx.x * blockDim.x + threadIdx.x;
    if (idx < MAT) g_Apow[MAT + idx] = A[idx];
}

// ---------------------------------------------------------------------------
// Tensor-core 256x256x256 fp32-in/out product tile via 3-limb bf16.
// C[128x128 tile at (by*128, bx*128)] = P @ R, all row-major 256x256.
// 256 threads, 8 warps of 32x64, K in 4 chunks of 64, in-kernel conversion.
// ---------------------------------------------------------------------------
__device__ void mma256_tile(const float* __restrict__ P,
                            const float* __restrict__ R,
                            float* __restrict__ C) {
    extern __shared__ char smem[];
    const uint32_t sb = smem_u32(smem);
    const int tid = threadIdx.x;
    const int wid = tid >> 5, lane = tid & 31;
    const int bm = blockIdx.y * 128;
    const int bn = blockIdx.x * 128;
    const int m0w = (wid & 3) * 32;
    const int n0w = (wid >> 2) * 64;

    uint32_t aoff[2][4], boff[4][4];
    {
        const uint32_t arow = (uint32_t)(m0w + (lane & 15)) * 128;
        const uint32_t khalf = (uint32_t)(lane >> 4) * 16;
#pragma unroll
        for (int mt = 0; mt < 2; mt++)
#pragma unroll
            for (int ks = 0; ks < 4; ks++)
                aoff[mt][ks] = swz(arow + (uint32_t)mt * 2048 + khalf + ks * 32);
        const uint32_t brow = (uint32_t)(n0w + (lane & 15)) * 128;
#pragma unroll
        for (int ng = 0; ng < 4; ng++)
#pragma unroll
            for (int ks = 0; ks < 4; ks++)
                boff[ng][ks] = swz(brow + (uint32_t)ng * 2048 + khalf + ks * 32);
    }

    float acc[2][8][4];
#pragma unroll
    for (int mt = 0; mt < 2; mt++)
#pragma unroll
        for (int nt = 0; nt < 8; nt++)
#pragma unroll
            for (int q = 0; q < 4; q++) acc[mt][nt][q] = 0.f;

    for (int kb = 0; kb < 256; kb += 64) {
        __syncthreads();   // protect smem from previous iteration's readers
        // P block: [r 0..127][k 0..63] -> Ph/Pl, packed uint2 writes
        {
            const int kq = (tid & 15) * 4;
#pragma unroll
            for (int it = 0; it < 8; it++) {
                const int r = it * 16 + (tid >> 4);
                float4 f = *(const float4*)&P[(size_t)(bm + r) * 256 + kb + kq];
                float v[4] = {f.x, f.y, f.z, f.w};
                unsigned short h[4], l[4];
#pragma unroll
                for (int q = 0; q < 4; q++) {
                    __nv_bfloat16 bh = __float2bfloat16(v[q]);
                    h[q] = bfb(bh);
                    l[q] = bfb(__float2bfloat16(v[q] - __bfloat162float(bh)));
                }
                uint2 ph, pl;
                ph.x = (uint32_t)h[0] | ((uint32_t)h[1] << 16);
                ph.y = (uint32_t)h[2] | ((uint32_t)h[3] << 16);
                pl.x = (uint32_t)l[0] | ((uint32_t)l[1] << 16);
                pl.y = (uint32_t)l[2] | ((uint32_t)l[3] << 16);
                const uint32_t off = swz((uint32_t)(r * 128 + kq * 2));
                *(uint2*)(smem + off) = ph;
                *(uint2*)(smem + PW_PL + off) = pl;
            }
        }
        // R block: global [k][n] -> smem [n][k] (transposed), 2B scattered
        {
            const int kr = tid >> 5;           // 0..7
            const int nq = (tid & 31) * 4;     // 0..124
#pragma unroll
            for (int it = 0; it < 8; it++) {
                const int k = it * 8 + kr;
                float4 f = *(const float4*)&R[(size_t)(kb + k) * 256 + bn + nq];
                float v[4] = {f.x, f.y, f.z, f.w};
#pragma unroll
                for (int q = 0; q < 4; q++) {
                    const int n = nq + q;
                    __nv_bfloat16 bh = __float2bfloat16(v[q]);
                    const uint32_t off = swz((uint32_t)(n * 128 + k * 2));
                    *(unsigned short*)(smem + PW_RH + off) = bfb(bh);
                    *(unsigned short*)(smem + PW_RL + off) =
                        bfb(__float2bfloat16(v[q] - __bfloat162float(bh)));
                }
            }
        }
        __syncthreads();
#pragma unroll
        for (int ks = 0; ks < 4; ks++) {
            uint32_t ah[2][4], al[2][4];
#pragma unroll
            for (int mt = 0; mt < 2; mt++) {
                ldm4(ah[mt], sb + aoff[mt][ks]);
                ldm4(al[mt], sb + PW_PL + aoff[mt][ks]);
            }
#pragma unroll
            for (int ng = 0; ng < 4; ng++) {
                uint32_t bh[4], bl[4];
                ldm4(bh, sb + PW_RH + boff[ng][ks]);
                ldm4(bl, sb + PW_RL + boff[ng][ks]);
#pragma unroll
                for (int mt = 0; mt < 2; mt++) {
                    mmabf(acc[mt][2 * ng + 0], ah[mt], bh[0], bh[2]);
                    mmabf(acc[mt][2 * ng + 1], ah[mt], bh[1], bh[3]);
                    mmabf(acc[mt][2 * ng + 0], ah[mt], bl[0], bl[2]);
                    mmabf(acc[mt][2 * ng + 1], ah[mt], bl[1], bl[3]);
                    mmabf(acc[mt][2 * ng + 0], al[mt], bh[0], bh[2]);
                    mmabf(acc[mt][2 * ng + 1], al[mt], bh[1], bh[3]);
                }
            }
        }
    }

    const int rbase = bm + m0w + (lane >> 2);
    const int cbase = bn + n0w + (lane & 3) * 2;
#pragma unroll
    for (int mt = 0; mt < 2; mt++) {
        const int r0 = rbase + mt * 16;
#pragma unroll
        for (int nt = 0; nt < 8; nt++) {
            const int c = cbase + nt * 8;
            *(float2*)&C[(size_t)r0 * 256 + c] =
                make_float2(acc[mt][nt][0], acc[mt][nt][1]);
            *(float2*)&C[(size_t)(r0 + 8) * 256 + c] =
                make_float2(acc[mt][nt][2], acc[mt][nt][3]);
        }
    }
}

// A^{d+j} = A^d @ A^j for j = 1..d   grid (2, 2, d), 256 threads, 64KB smem
__global__ __launch_bounds__(256) void pow_mma_kernel(int d) {
    const int j = blockIdx.z + 1;
    mma256_tile(g_Apow + (size_t)d * MAT, g_Apow + (size_t)j * MAT,
                g_Apow + (size_t)(d + j) * MAT);
}

// ---------------------------------------------------------------------------
// fp32 32x32-tile GEMM (Horner combine): C = Am @ Bt^T + bias
// ---------------------------------------------------------------------------
__device__ __forceinline__ void gemm32_ntr(const float* __restrict__ Am,
                                           const float* __restrict__ Bt,
                                           float* __restrict__ Cm,
                                           const float* __restrict__ bias,
                                           int brow, int bcol) {
    __shared__ float As[16][33];
    __shared__ float Bs[16][33];
    const int tid = threadIdx.x;
    const int ty = tid >> 4, tx = tid & 15;
    const int ar = tid >> 3;            // 0..31
    const int ak = (tid & 7) * 2;       // 0..14
    float acc[2][2] = {};
    for (int k0 = 0; k0 < 256; k0 += 16) {
        float2 a2 = *(const float2*)&Am[(size_t)(brow + ar) * 256 + k0 + ak];
        As[ak][ar] = a2.x; As[ak + 1][ar] = a2.y;
        float2 b2 = *(const float2*)&Bt[(size_t)(bcol + ar) * 256 + k0 + ak];
        Bs[ak][ar] = b2.x; Bs[ak + 1][ar] = b2.y;
        __syncthreads();
#pragma unroll
        for (int k = 0; k < 16; k++) {
            float a0 = As[k][ty * 2], a1 = As[k][ty * 2 + 1];
            float b0 = Bs[k][tx * 2], b1 = Bs[k][tx * 2 + 1];
            acc[0][0] += a0 * b0; acc[0][1] += a0 * b1;
            acc[1][0] += a1 * b0; acc[1][1] += a1 * b1;
        }
        __syncthreads();
    }
#pragma unroll
    for (int ii = 0; ii < 2; ii++) {
        const size_t off = (size_t)(brow + ty * 2 + ii) * 256 + bcol + tx * 2;
        float2 b = *(const float2*)&bias[off];
        float2 v = make_float2(acc[ii][0] + b.x, acc[ii][1] + b.y);
        *(float2*)&Cm[off] = v;
    }
}

// Horner: H[i+1] = H[i] @ (A^128)^T + S[i+1]   grid (8, 16)
__global__ void combine_step_kernel(int i) {
    gemm32_ntr(g_H + (size_t)i * (512 * 256),
               g_Apow + (size_t)128 * MAT,
               g_H + (size_t)(i + 1) * (512 * 256),
               g_S + (size_t)(i + 1) * (512 * 256),
               blockIdx.y * 32, blockIdx.x * 32);
}

__global__ void v_kernel(const float* __restrict__ Bv) {
    __shared__ float bs[256];
    int j = blockIdx.x, n = threadIdx.x;
    bs[n] = Bv[n];
    __syncthreads();
    if (j == 0) { g_V[n] = bs[n]; return; }
    const float* Am = g_Apow + (size_t)j * MAT;
    float s = 0.f;
#pragma unroll 8
    for (int m = 0; m < 256; m++) s += Am[n * 256 + m] * bs[m];
    g_V[j * 256 + n] = s;
}

__global__ void s_kernel(const float* __restrict__ inp) {
    __shared__ float fs[128];
    int r = blockIdx.x, i = blockIdx.y, n = threadIdx.x;
    if (n < 128) fs[n] = inp[r * 1024 + i * T_CH + n];
    __syncthreads();
    float s = 0.f;
#pragma unroll 4
    for (int k = 0; k < 128; k++)
        s += g_V[(127 - k) * 256 + n] * fs[k];
    g_S[(i * 512 + r) * 256 + n] = s;
    if (i == 0) g_H[r * 256 + n] = s;   // H[0] = S[0]
}

// ---------------------------------------------------------------------------
// packers (fp16 single limb), SW128-swizzled, exact smem image.
// ---------------------------------------------------------------------------
__global__ void b_limbs_kernel() {
    const int blk = blockIdx.x;            // t*6 + kc
    const int t = blk / NCHUNK, kc = blk % NCHUNK;
    const int tid = threadIdx.x;
    const int kk0 = (tid & 15) * 4;
    char* dh = (char*)g_Bh + (size_t)blk * BB_BLK;
    for (int it = 0; it < 16; it++) {
        int n = it * 16 + (tid >> 4);
        float v[4];
        if (kc < 2) {
            int k0 = kc * 64 + kk0;
#pragma unroll
            for (int q = 0; q < 4; q++) {
                int k = k0 + q;
                v[q] = (k <= t) ? g_V[(t - k) * 256 + n] : 0.f;
            }
        } else {
            int m0 = kc * 64 + kk0 - 128;
            float4 a4 = *(const float4*)&g_Apow[(size_t)(t + 1) * MAT + n * 256 + m0];
            v[0] = a4.x; v[1] = a4.y; v[2] = a4.z; v[3] = a4.w;
        }
        uint2 ph;
        ph.x = (uint32_t)hbits(v[0]) | ((uint32_t)hbits(v[1]) << 16);
        ph.y = (uint32_t)hbits(v[2]) | ((uint32_t)hbits(v[3]) << 16);
        uint32_t off = swz((uint32_t)(n * 128 + kk0 * 2));
        *(uint2*)(dh + off) = ph;
    }
}

__global__ void a_limbs_kernel(const float* __restrict__ inp) {
    const int blk = blockIdx.x;            // rt*6 + kc
    const int rt = blk / NCHUNK, kc = blk % NCHUNK;
    const int i = rt >> 2;
    const int tid = threadIdx.x;
    const int kk0 = (tid & 15) * 4;
    char* dh = (char*)g_Ah + (size_t)blk * AB_BLK;
    for (int it = 0; it < 8; it++) {
        int row = it * 16 + (tid >> 4);
        int r = (rt & 3) * 128 + row;
        float v[4];
        if (kc < 2) {
            float4 f4 = *(const float4*)&inp[r * 1024 + i * 128 + kc * 64 + kk0];
            v[0] = f4.x; v[1] = f4.y; v[2] = f4.z; v[3] = f4.w;
        } else if (i == 0) {
            v[0] = v[1] = v[2] = v[3] = 0.f;
        } else {
            float4 f4 = *(const float4*)&g_H[(size_t)((i - 1) * 512 + r) * 256 +
                                             (kc - 2) * 64 + kk0];
            v[0] = f4.x; v[1] = f4.y; v[2] = f4.z; v[3] = f4.w;
        }
        uint2 ph;
        ph.x = (uint32_t)hbits(v[0]) | ((uint32_t)hbits(v[1]) << 16);
        ph.y = (uint32_t)hbits(v[2]) | ((uint32_t)hbits(v[3]) << 16);
        uint32_t off = swz((uint32_t)(row * 128 + kk0 * 2));
        *(uint2*)(dh + off) = ph;
    }
}

// ---------------------------------------------------------------------------
// Main GEMM: fp16 SINGLE-limb mma.sync. CTA = 128x256 out tile, 512 threads
// (16 warps, 32x64 warp tiles), 3-stage cp.async pipeline. Causal skip at
// chunk level (kc=1 for t<64) AND k16-step level inside W-chunks.
// grid (128 t-tiles, 32 row tiles).     [unchanged — passing since round 8]
// ---------------------------------------------------------------------------
__global__ __launch_bounds__(512, 1) void main_mma_kernel(float* __restrict__ out) {
    extern __shared__ char smem[];
    const uint32_t sb = smem_u32(smem);
    const int tid = threadIdx.x;
    const int wid = tid >> 5;
    const int lane = tid & 31;
    const int t = blockIdx.x;
    const int by = blockIdx.y;

    const int m0w = (wid & 3) * 32;
    const int n0w = (wid >> 2) * 64;

    int clist[6] = {0, 1, 2, 3, 4, 5};
    int nch = 6;
    if (t < 64) { clist[1] = 2; clist[2] = 3; clist[3] = 4; clist[4] = 5; nch = 5; }

    const int nks_c0 = min(4, (t >> 4) + 1);
    const int nks_c1 = (t < 64) ? 0 : min(4, ((t - 64) >> 4) + 1);

    const char* Asrc = (const char*)g_Ah + (size_t)by * NCHUNK * AB_BLK;
    const char* Bsrc = (const char*)g_Bh + (size_t)t * NCHUNK * BB_BLK;

    const uint32_t cpo = (uint32_t)tid * 16;

    uint32_t aoff[2][4];
    uint32_t boff[4][4];
    {
        const uint32_t arow = (uint32_t)(m0w + (lane & 15)) * 128;
        const uint32_t khalf = (uint32_t)(lane >> 4) * 16;
#pragma unroll
        for (int mt = 0; mt < 2; mt++)
#pragma unroll
            for (int ks = 0; ks < 4; ks++)
                aoff[mt][ks] = swz(arow + (uint32_t)mt * 2048 + khalf + ks * 32);
        const uint32_t brow = (uint32_t)(n0w + (lane & 15)) * 128;
#pragma unroll
        for (int ng = 0; ng < 4; ng++)
#pragma unroll
            for (int ks = 0; ks < 4; ks++)
                boff[ng][ks] = swz(brow + (uint32_t)ng * 2048 + khalf + ks * 32);
    }

    float acc[2][8][4];
#pragma unroll
    for (int mt = 0; mt < 2; mt++)
#pragma unroll
        for (int nt = 0; nt < 8; nt++)
#pragma unroll
            for (int q = 0; q < 4; q++) acc[mt][nt][q] = 0.f;

#define LOAD_STAGE(kc, st)                                                      \
    do {                                                                        \
        uint32_t s0 = sb + (uint32_t)(st) * ST_SZ;                              \
        const char* ga = Asrc + (size_t)(kc) * AB_BLK;                          \
        const char* gc = Bsrc + (size_t)(kc) * BB_BLK;                          \
        cp16(s0 + cpo, ga + cpo);                                               \
        cp16(s0 + 8192 + cpo, ga + 8192 + cpo);                                 \
        _Pragma("unroll")                                                       \
        for (int q = 0; q < 4; q++)                                             \
            cp16(s0 + ST_B + q * 8192 + cpo, gc + q * 8192 + cpo);              \
        CP_COMMIT();                                                            \
    } while (0)

    LOAD_STAGE(clist[0], 0);
    LOAD_STAGE(clist[1], 1);

    for (int j = 0; j < nch; j++) {
        if (j + NSTG - 1 < nch) {
            LOAD_STAGE(clist[j + NSTG - 1], (j + NSTG - 1) % NSTG);
            CP_WAIT(2);
        } else if (j == nch - 2) {
            CP_WAIT(1);
        } else {
            CP_WAIT(0);
        }
        __syncthreads();
        const uint32_t st = sb + (uint32_t)(j % NSTG) * ST_SZ;
        const int kc = clist[j];
        const int nks = (kc == 0) ? nks_c0 : ((kc == 1) ? nks_c1 : 4);
#pragma unroll
        for (int ks = 0; ks < 4; ks++) {
            if (ks >= nks) break;
            uint32_t ah[2][4];
            ldm4(ah[0], st + aoff[0][ks]);
            ldm4(ah[1], st + aoff[1][ks]);
#pragma unroll
            for (int ng = 0; ng < 4; ng++) {
                uint32_t bh[4];
                ldm4(bh, st + ST_B + boff[ng][ks]);
#pragma unroll
                for (int mt = 0; mt < 2; mt++) {
                    mma16816(acc[mt][2 * ng + 0], ah[mt], bh[0], bh[2]);
                    mma16816(acc[mt][2 * ng + 1], ah[mt], bh[1], bh[3]);
                }
            }
        }
        __syncthreads();
    }
#undef LOAD_STAGE

    const int i_ch = by >> 2;
    float* ob = out + (size_t)(i_ch * 128 + t) * 131072;
    const int rbase = (by & 3) * 128 + m0w + (lane >> 2);
    const int cbase = n0w + (lane & 3) * 2;
#pragma unroll
    for (int mt = 0; mt < 2; mt++) {
        const int r0 = rbase + mt * 16;
#pragma unroll
        for (int nt = 0; nt < 8; nt++) {
            const int c = cbase + nt * 8;
            float2 v0 = make_float2(acc[mt][nt][0], acc[mt][nt][1]);
            float2 v1 = make_float2(acc[mt][nt][2], acc[mt][nt][3]);
            __stcs((float2*)(ob + (size_t)r0 * 256 + c), v0);
            __stcs((float2*)(ob + (size_t)(r0 + 8) * 256 + c), v1);
        }
    }
}

// ---------------------------------------------------------------------------
extern "C" void kernel_launch(void* const* d_in, const int* in_sizes, int n_in,
                              void* d_out, int out_size) {
    const float* inp = (const float*)d_in[0];   // (8,64,1024)
    const float* A   = (const float*)d_in[1];   // (256,256)
    const float* Bv  = (const float*)d_in[2];   // (256,)
    float* out = (float*)d_out;

    cudaFuncSetAttribute(main_mma_kernel,
                         cudaFuncAttributeMaxDynamicSharedMemorySize, SMEM_SZ);
    cudaFuncSetAttribute(pow_mma_kernel,
                         cudaFuncAttributeMaxDynamicSharedMemorySize, PW_SMEM);

    init_a_kernel<<<256, 256>>>(A);
    for (int d = 1; d <= 64; d <<= 1)
        pow_mma_kernel<<<dim3(2, 2, d), 256, PW_SMEM>>>(d);

    v_kernel<<<128, 256>>>(Bv);
    b_limbs_kernel<<<128 * NCHUNK, 256>>>();
    s_kernel<<<dim3(512, 8), 256>>>(inp);
    for (int i = 0; i < 7; i++)                 // H[1..7] via Horner
        combine_step_kernel<<<dim3(8, 16), 256>>>(i);
    a_limbs_kernel<<<32 * NCHUNK, 256>>>(inp);

    main_mma_kernel<<<dim3(128, 32), 512, SMEM_SZ>>>(out);
}

// round 11
// speedup vs baseline: 1.7210x; 1.2274x over previous
#include <cuda_runtime.h>
#include <cuda_fp16.h>
#include <cuda_bf16.h>
#include <cstdint>

// ---------------------------------------------------------------------------
// HiPPO-LegT: chunked convolution + one big GEMM.
// Main GEMM: mma.sync fp16 single limb (Ah*Bh, fp32 acc) + causal skips.
// Pow chain (A^1..A^128): tensor-core 3-limb bf16; R operand kept row-major
// [k][n] in smem (packed uint2 conversion stores) and loaded via
// ldmatrix.x4.trans — no transpose scatter.
// Combine: Horner H[i+1] = H[i] (A^128)^T + S[i+1] on 32x32 fp32 tiles.
// ---------------------------------------------------------------------------

#define N_ST   256
#define T_CH   128
#define MAT    65536
#define NCHUNK 6
#define AB_BLK 16384              // bytes: 128 rows x 64 k fp16 (swizzled)
#define BB_BLK 32768              // bytes: 256 rows x 64 k fp16 (swizzled)

// main mma kernel smem: per stage [Ah 16K][B 32K], 3 stages
#define ST_B   16384
#define ST_SZ  49152
#define NSTG   3
#define SMEM_SZ (NSTG * ST_SZ)

// pow mma kernel smem: [Ph 16K][Pl 16K][Rh 16K][Rl 16K]
#define PW_PL  16384
#define PW_RH  32768
#define PW_RL  49152
#define PW_SMEM 65536

// ---- device scratch ----
__device__ __align__(256) float g_Apow[129 * MAT];     // A^1..A^128 at 1..128
__device__ __align__(256) float g_V[T_CH * N_ST];      // v_j = A^j B
__device__ __align__(256) float g_S[8 * 512 * N_ST];
__device__ __align__(256) float g_H[8 * 512 * N_ST];
__device__ __align__(256) __half g_Ah[(size_t)32 * NCHUNK * 8192];
__device__ __align__(256) __half g_Bh[(size_t)128 * NCHUNK * 16384];

// ---------------------------------------------------------------------------
__device__ __forceinline__ uint32_t smem_u32(const void* p) {
    uint32_t a;
    asm("{ .reg .u64 t; cvta.to.shared.u64 t, %1; cvt.u32.u64 %0, t; }" : "=r"(a) : "l"(p));
    return a;
}
__device__ __forceinline__ void cp16(uint32_t s, const void* g) {
    asm volatile("cp.async.cg.shared.global [%0], [%1], 16;" :: "r"(s), "l"(g));
}
#define CP_COMMIT() asm volatile("cp.async.commit_group;" ::: "memory")
#define CP_WAIT(n)  asm volatile("cp.async.wait_group %0;" :: "n"(n) : "memory")

__device__ __forceinline__ void ldm4(uint32_t* r, uint32_t addr) {
    asm volatile("ldmatrix.sync.aligned.m8n8.x4.shared.b16 {%0,%1,%2,%3}, [%4];"
                 : "=r"(r[0]), "=r"(r[1]), "=r"(r[2]), "=r"(r[3]) : "r"(addr));
}
__device__ __forceinline__ void ldm4t(uint32_t* r, uint32_t addr) {
    asm volatile("ldmatrix.sync.aligned.m8n8.x4.trans.shared.b16 {%0,%1,%2,%3}, [%4];"
                 : "=r"(r[0]), "=r"(r[1]), "=r"(r[2]), "=r"(r[3]) : "r"(addr));
}
__device__ __forceinline__ void mma16816(float* d, const uint32_t* a,
                                         uint32_t b0, uint32_t b1) {
    asm volatile(
        "mma.sync.aligned.m16n8k16.row.col.f32.f16.f16.f32 "
        "{%0,%1,%2,%3}, {%4,%5,%6,%7}, {%8,%9}, {%0,%1,%2,%3};"
        : "+f"(d[0]), "+f"(d[1]), "+f"(d[2]), "+f"(d[3])
        : "r"(a[0]), "r"(a[1]), "r"(a[2]), "r"(a[3]), "r"(b0), "r"(b1));
}
__device__ __forceinline__ void mmabf(float* d, const uint32_t* a,
                                      uint32_t b0, uint32_t b1) {
    asm volatile(
        "mma.sync.aligned.m16n8k16.row.col.f32.bf16.bf16.f32 "
        "{%0,%1,%2,%3}, {%4,%5,%6,%7}, {%8,%9}, {%0,%1,%2,%3};"
        : "+f"(d[0]), "+f"(d[1]), "+f"(d[2]), "+f"(d[3])
        : "r"(a[0]), "r"(a[1]), "r"(a[2]), "r"(a[3]), "r"(b0), "r"(b1));
}

__device__ __forceinline__ uint32_t swz(uint32_t off) { return off ^ ((off >> 3) & 0x70); }

__device__ __forceinline__ unsigned short hbits(float x) {
    __half h = __float2half_rn(x);
    return *reinterpret_cast<unsigned short*>(&h);
}
__device__ __forceinline__ unsigned short bfb(__nv_bfloat16 b) {
    return *reinterpret_cast<unsigned short*>(&b);
}

// ---------------------------------------------------------------------------
__global__ void init_a_kernel(const float* __restrict__ A) {
    int idx = blockIdx.x * blockDim.x + threadIdx.x;
    if (idx < MAT) g_Apow[MAT + idx] = A[idx];
}

// ---------------------------------------------------------------------------
// Tensor-core 256x256x256 fp32-in/out product tile via 3-limb bf16.
// C[128x128 tile at (by*128, bx*128)] = P @ R, all row-major 256x256.
// R stored row-major [k][n] in two 64-col panels (128B rows), loaded with
// ldmatrix.trans. 256 threads, 8 warps of 32x64, K in 4 chunks of 64.
// ---------------------------------------------------------------------------
__device__ void mma256_tile(const float* __restrict__ P,
                            const float* __restrict__ R,
                            float* __restrict__ C) {
    extern __shared__ char smem[];
    const uint32_t sb = smem_u32(smem);
    const int tid = threadIdx.x;
    const int wid = tid >> 5, lane = tid & 31;
    const int bm = blockIdx.y * 128;
    const int bn = blockIdx.x * 128;
    const int m0w = (wid & 3) * 32;
    const int n0w = (wid >> 2) * 64;                  // 0 or 64 -> panel
    const uint32_t rpH = sb + PW_RH + (uint32_t)(n0w >> 6) * 8192;
    const uint32_t rpL = sb + PW_RL + (uint32_t)(n0w >> 6) * 8192;

    // A fragment offsets (non-trans, [m][k] 128B rows)
    uint32_t aoff[2][4];
    {
        const uint32_t arow = (uint32_t)(m0w + (lane & 15)) * 128;
        const uint32_t khalf = (uint32_t)(lane >> 4) * 16;
#pragma unroll
        for (int mt = 0; mt < 2; mt++)
#pragma unroll
            for (int ks = 0; ks < 4; ks++)
                aoff[mt][ks] = swz(arow + (uint32_t)mt * 2048 + khalf + ks * 32);
    }
    // B fragment offsets (trans, [k][nl] 128B rows within panel):
    // matrices M0..M3: lane j=lane>>3 selects matrix, i=lane&7 its row.
    // M0: k 0-7 / n 0-7 ; M1: k 8-15 / n 0-7 ; M2: k 0-7 / n 8-15 ; M3: k 8-15 / n 8-15
    uint32_t boff[4][4];
    {
        const int i = lane & 7, jm = lane >> 3;
        const uint32_t kl = (uint32_t)(i + (jm & 1) * 8);
        const uint32_t nb = (uint32_t)((jm >> 1) * 8);
#pragma unroll
        for (int ng = 0; ng < 4; ng++)
#pragma unroll
            for (int ks = 0; ks < 4; ks++)
                boff[ng][ks] = swz((uint32_t)(ks * 16 + kl) * 128 +
                                   (uint32_t)(ng * 16 + nb) * 2);
    }

    float acc[2][8][4];
#pragma unroll
    for (int mt = 0; mt < 2; mt++)
#pragma unroll
        for (int nt = 0; nt < 8; nt++)
#pragma unroll
            for (int q = 0; q < 4; q++) acc[mt][nt][q] = 0.f;

    for (int kb = 0; kb < 256; kb += 64) {
        __syncthreads();   // protect smem from previous iteration's readers
        // P block: [r 0..127][k 0..63] -> Ph/Pl, packed uint2 writes
        {
            const int kq = (tid & 15) * 4;
#pragma unroll
            for (int it = 0; it < 8; it++) {
                const int r = it * 16 + (tid >> 4);
                float4 f = *(const float4*)&P[(size_t)(bm + r) * 256 + kb + kq];
                float v[4] = {f.x, f.y, f.z, f.w};
                unsigned short h[4], l[4];
#pragma unroll
                for (int q = 0; q < 4; q++) {
                    __nv_bfloat16 bh = __float2bfloat16(v[q]);
                    h[q] = bfb(bh);
                    l[q] = bfb(__float2bfloat16(v[q] - __bfloat162float(bh)));
                }
                uint2 ph, pl;
                ph.x = (uint32_t)h[0] | ((uint32_t)h[1] << 16);
                ph.y = (uint32_t)h[2] | ((uint32_t)h[3] << 16);
                pl.x = (uint32_t)l[0] | ((uint32_t)l[1] << 16);
                pl.y = (uint32_t)l[2] | ((uint32_t)l[3] << 16);
                const uint32_t off = swz((uint32_t)(r * 128 + kq * 2));
                *(uint2*)(smem + off) = ph;
                *(uint2*)(smem + PW_PL + off) = pl;
            }
        }
        // R block: global [k][n] -> smem row-major panels, packed uint2
        {
            const int nq = (tid & 31) * 4;     // 0..124
            const int pan = nq >> 6;           // 0/1
            const int nl = nq & 63;
#pragma unroll
            for (int it = 0; it < 8; it++) {
                const int k = it * 8 + (tid >> 5);
                float4 f = *(const float4*)&R[(size_t)(kb + k) * 256 + bn + nq];
                float v[4] = {f.x, f.y, f.z, f.w};
                unsigned short h[4], l[4];
#pragma unroll
                for (int q = 0; q < 4; q++) {
                    __nv_bfloat16 bh = __float2bfloat16(v[q]);
                    h[q] = bfb(bh);
                    l[q] = bfb(__float2bfloat16(v[q] - __bfloat162float(bh)));
                }
                uint2 rh, rl;
                rh.x = (uint32_t)h[0] | ((uint32_t)h[1] << 16);
                rh.y = (uint32_t)h[2] | ((uint32_t)h[3] << 16);
                rl.x = (uint32_t)l[0] | ((uint32_t)l[1] << 16);
                rl.y = (uint32_t)l[2] | ((uint32_t)l[3] << 16);
                const uint32_t off = (uint32_t)pan * 8192 +
                                     swz((uint32_t)(k * 128 + nl * 2));
                *(uint2*)(smem + PW_RH + off) = rh;
                *(uint2*)(smem + PW_RL + off) = rl;
            }
        }
        __syncthreads();
#pragma unroll
        for (int ks = 0; ks < 4; ks++) {
            uint32_t ah[2][4], al[2][4];
#pragma unroll
            for (int mt = 0; mt < 2; mt++) {
                ldm4(ah[mt], sb + aoff[mt][ks]);
                ldm4(al[mt], sb + PW_PL + aoff[mt][ks]);
            }
#pragma unroll
            for (int ng = 0; ng < 4; ng++) {
                uint32_t bh[4], bl[4];
                ldm4t(bh, rpH + boff[ng][ks]);
                ldm4t(bl, rpL + boff[ng][ks]);
#pragma unroll
                for (int mt = 0; mt < 2; mt++) {
                    mmabf(acc[mt][2 * ng + 0], ah[mt], bh[0], bh[1]);
                    mmabf(acc[mt][2 * ng + 1], ah[mt], bh[2], bh[3]);
                    mmabf(acc[mt][2 * ng + 0], ah[mt], bl[0], bl[1]);
                    mmabf(acc[mt][2 * ng + 1], ah[mt], bl[2], bl[3]);
                    mmabf(acc[mt][2 * ng + 0], al[mt], bh[0], bh[1]);
                    mmabf(acc[mt][2 * ng + 1], al[mt], bh[2], bh[3]);
                }
            }
        }
    }

    const int rbase = bm + m0w + (lane >> 2);
    const int cbase = bn + n0w + (lane & 3) * 2;
#pragma unroll
    for (int mt = 0; mt < 2; mt++) {
        const int r0 = rbase + mt * 16;
#pragma unroll
        for (int nt = 0; nt < 8; nt++) {
            const int c = cbase + nt * 8;
            *(float2*)&C[(size_t)r0 * 256 + c] =
                make_float2(acc[mt][nt][0], acc[mt][nt][1]);
            *(float2*)&C[(size_t)(r0 + 8) * 256 + c] =
                make_float2(acc[mt][nt][2], acc[mt][nt][3]);
        }
    }
}

// A^{d+j} = A^d @ A^j for j = 1..d   grid (2, 2, d), 256 threads, 64KB smem
__global__ __launch_bounds__(256) void pow_mma_kernel(int d) {
    const int j = blockIdx.z + 1;
    mma256_tile(g_Apow + (size_t)d * MAT, g_Apow + (size_t)j * MAT,
                g_Apow + (size_t)(d + j) * MAT);
}

// ---------------------------------------------------------------------------
// fp32 32x32-tile GEMM (Horner combine): C = Am @ Bt^T + bias
// ---------------------------------------------------------------------------
__device__ __forceinline__ void gemm32_ntr(const float* __restrict__ Am,
                                           const float* __restrict__ Bt,
                                           float* __restrict__ Cm,
                                           const float* __restrict__ bias,
                                           int brow, int bcol) {
    __shared__ float As[16][33];
    __shared__ float Bs[16][33];
    const int tid = threadIdx.x;
    const int ty = tid >> 4, tx = tid & 15;
    const int ar = tid >> 3;            // 0..31
    const int ak = (tid & 7) * 2;       // 0..14
    float acc[2][2] = {};
    for (int k0 = 0; k0 < 256; k0 += 16) {
        float2 a2 = *(const float2*)&Am[(size_t)(brow + ar) * 256 + k0 + ak];
        As[ak][ar] = a2.x; As[ak + 1][ar] = a2.y;
        float2 b2 = *(const float2*)&Bt[(size_t)(bcol + ar) * 256 + k0 + ak];
        Bs[ak][ar] = b2.x; Bs[ak + 1][ar] = b2.y;
        __syncthreads();
#pragma unroll
        for (int k = 0; k < 16; k++) {
            float a0 = As[k][ty * 2], a1 = As[k][ty * 2 + 1];
            float b0 = Bs[k][tx * 2], b1 = Bs[k][tx * 2 + 1];
            acc[0][0] += a0 * b0; acc[0][1] += a0 * b1;
            acc[1][0] += a1 * b0; acc[1][1] += a1 * b1;
        }
        __syncthreads();
    }
#pragma unroll
    for (int ii = 0; ii < 2; ii++) {
        const size_t off = (size_t)(brow + ty * 2 + ii) * 256 + bcol + tx * 2;
        float2 b = *(const float2*)&bias[off];
        float2 v = make_float2(acc[ii][0] + b.x, acc[ii][1] + b.y);
        *(float2*)&Cm[off] = v;
    }
}

// Horner: H[i+1] = H[i] @ (A^128)^T + S[i+1]   grid (8, 16)
__global__ void combine_step_kernel(int i) {
    gemm32_ntr(g_H + (size_t)i * (512 * 256),
               g_Apow + (size_t)128 * MAT,
               g_H + (size_t)(i + 1) * (512 * 256),
               g_S + (size_t)(i + 1) * (512 * 256),
               blockIdx.y * 32, blockIdx.x * 32);
}

__global__ void v_kernel(const float* __restrict__ Bv) {
    __shared__ float bs[256];
    int j = blockIdx.x, n = threadIdx.x;
    bs[n] = Bv[n];
    __syncthreads();
    if (j == 0) { g_V[n] = bs[n]; return; }
    const float* Am = g_Apow + (size_t)j * MAT;
    float s = 0.f;
#pragma unroll 8
    for (int m = 0; m < 256; m++) s += Am[n * 256 + m] * bs[m];
    g_V[j * 256 + n] = s;
}

__global__ void s_kernel(const float* __restrict__ inp) {
    __shared__ float fs[128];
    int r = blockIdx.x, i = blockIdx.y, n = threadIdx.x;
    if (n < 128) fs[n] = inp[r * 1024 + i * T_CH + n];
    __syncthreads();
    float s = 0.f;
#pragma unroll 4
    for (int k = 0; k < 128; k++)
        s += g_V[(127 - k) * 256 + n] * fs[k];
    g_S[(i * 512 + r) * 256 + n] = s;
    if (i == 0) g_H[r * 256 + n] = s;   // H[0] = S[0]
}

// ---------------------------------------------------------------------------
// packers (fp16 single limb), SW128-swizzled, exact smem image.
// ---------------------------------------------------------------------------
__global__ void b_limbs_kernel() {
    const int blk = blockIdx.x;            // t*6 + kc
    const int t = blk / NCHUNK, kc = blk % NCHUNK;
    const int tid = threadIdx.x;
    const int kk0 = (tid & 15) * 4;
    char* dh = (char*)g_Bh + (size_t)blk * BB_BLK;
    for (int it = 0; it < 16; it++) {
        int n = it * 16 + (tid >> 4);
        float v[4];
        if (kc < 2) {
            int k0 = kc * 64 + kk0;
#pragma unroll
            for (int q = 0; q < 4; q++) {
                int k = k0 + q;
                v[q] = (k <= t) ? g_V[(t - k) * 256 + n] : 0.f;
            }
        } else {
            int m0 = kc * 64 + kk0 - 128;
            float4 a4 = *(const float4*)&g_Apow[(size_t)(t + 1) * MAT + n * 256 + m0];
            v[0] = a4.x; v[1] = a4.y; v[2] = a4.z; v[3] = a4.w;
        }
        uint2 ph;
        ph.x = (uint32_t)hbits(v[0]) | ((uint32_t)hbits(v[1]) << 16);
        ph.y = (uint32_t)hbits(v[2]) | ((uint32_t)hbits(v[3]) << 16);
        uint32_t off = swz((uint32_t)(n * 128 + kk0 * 2));
        *(uint2*)(dh + off) = ph;
    }
}

__global__ void a_limbs_kernel(const float* __restrict__ inp) {
    const int blk = blockIdx.x;            // rt*6 + kc
    const int rt = blk / NCHUNK, kc = blk % NCHUNK;
    const int i = rt >> 2;
    const int tid = threadIdx.x;
    const int kk0 = (tid & 15) * 4;
    char* dh = (char*)g_Ah + (size_t)blk * AB_BLK;
    for (int it = 0; it < 8; it++) {
        int row = it * 16 + (tid >> 4);
        int r = (rt & 3) * 128 + row;
        float v[4];
        if (kc < 2) {
            float4 f4 = *(const float4*)&inp[r * 1024 + i * 128 + kc * 64 + kk0];
            v[0] = f4.x; v[1] = f4.y; v[2] = f4.z; v[3] = f4.w;
        } else if (i == 0) {
            v[0] = v[1] = v[2] = v[3] = 0.f;
        } else {
            float4 f4 = *(const float4*)&g_H[(size_t)((i - 1) * 512 + r) * 256 +
                                             (kc - 2) * 64 + kk0];
            v[0] = f4.x; v[1] = f4.y; v[2] = f4.z; v[3] = f4.w;
        }
        uint2 ph;
        ph.x = (uint32_t)hbits(v[0]) | ((uint32_t)hbits(v[1]) << 16);
        ph.y = (uint32_t)hbits(v[2]) | ((uint32_t)hbits(v[3]) << 16);
        uint32_t off = swz((uint32_t)(row * 128 + kk0 * 2));
        *(uint2*)(dh + off) = ph;
    }
}

// ---------------------------------------------------------------------------
// Main GEMM: fp16 SINGLE-limb mma.sync. CTA = 128x256 out tile, 512 threads
// (16 warps, 32x64 warp tiles), 3-stage cp.async pipeline. Causal skip at
// chunk level (kc=1 for t<64) AND k16-step level inside W-chunks.
// grid (128 t-tiles, 32 row tiles).     [unchanged — passing since round 8]
// ---------------------------------------------------------------------------
__global__ __launch_bounds__(512, 1) void main_mma_kernel(float* __restrict__ out) {
    extern __shared__ char smem[];
    const uint32_t sb = smem_u32(smem);
    const int tid = threadIdx.x;
    const int wid = tid >> 5;
    const int lane = tid & 31;
    const int t = blockIdx.x;
    const int by = blockIdx.y;

    const int m0w = (wid & 3) * 32;
    const int n0w = (wid >> 2) * 64;

    int clist[6] = {0, 1, 2, 3, 4, 5};
    int nch = 6;
    if (t < 64) { clist[1] = 2; clist[2] = 3; clist[3] = 4; clist[4] = 5; nch = 5; }

    const int nks_c0 = min(4, (t >> 4) + 1);
    const int nks_c1 = (t < 64) ? 0 : min(4, ((t - 64) >> 4) + 1);

    const char* Asrc = (const char*)g_Ah + (size_t)by * NCHUNK * AB_BLK;
    const char* Bsrc = (const char*)g_Bh + (size_t)t * NCHUNK * BB_BLK;

    const uint32_t cpo = (uint32_t)tid * 16;

    uint32_t aoff[2][4];
    uint32_t boff[4][4];
    {
        const uint32_t arow = (uint32_t)(m0w + (lane & 15)) * 128;
        const uint32_t khalf = (uint32_t)(lane >> 4) * 16;
#pragma unroll
        for (int mt = 0; mt < 2; mt++)
#pragma unroll
            for (int ks = 0; ks < 4; ks++)
                aoff[mt][ks] = swz(arow + (uint32_t)mt * 2048 + khalf + ks * 32);
        const uint32_t brow = (uint32_t)(n0w + (lane & 15)) * 128;
#pragma unroll
        for (int ng = 0; ng < 4; ng++)
#pragma unroll
            for (int ks = 0; ks < 4; ks++)
                boff[ng][ks] = swz(brow + (uint32_t)ng * 2048 + khalf + ks * 32);
    }

    float acc[2][8][4];
#pragma unroll
    for (int mt = 0; mt < 2; mt++)
#pragma unroll
        for (int nt = 0; nt < 8; nt++)
#pragma unroll
            for (int q = 0; q < 4; q++) acc[mt][nt][q] = 0.f;

#define LOAD_STAGE(kc, st)                                                      \
    do {                                                                        \
        uint32_t s0 = sb + (uint32_t)(st) * ST_SZ;                              \
        const char* ga = Asrc + (size_t)(kc) * AB_BLK;                          \
        const char* gc = Bsrc + (size_t)(kc) * BB_BLK;                          \
        cp16(s0 + cpo, ga + cpo);                                               \
        cp16(s0 + 8192 + cpo, ga + 8192 + cpo);                                 \
        _Pragma("unroll")                                                       \
        for (int q = 0; q < 4; q++)                                             \
            cp16(s0 + ST_B + q * 8192 + cpo, gc + q * 8192 + cpo);              \
        CP_COMMIT();                                                            \
    } while (0)

    LOAD_STAGE(clist[0], 0);
    LOAD_STAGE(clist[1], 1);

    for (int j = 0; j < nch; j++) {
        if (j + NSTG - 1 < nch) {
            LOAD_STAGE(clist[j + NSTG - 1], (j + NSTG - 1) % NSTG);
            CP_WAIT(2);
        } else if (j == nch - 2) {
            CP_WAIT(1);
        } else {
            CP_WAIT(0);
        }
        __syncthreads();
        const uint32_t st = sb + (uint32_t)(j % NSTG) * ST_SZ;
        const int kc = clist[j];
        const int nks = (kc == 0) ? nks_c0 : ((kc == 1) ? nks_c1 : 4);
#pragma unroll
        for (int ks = 0; ks < 4; ks++) {
            if (ks >= nks) break;
            uint32_t ah[2][4];
            ldm4(ah[0], st + aoff[0][ks]);
            ldm4(ah[1], st + aoff[1][ks]);
#pragma unroll
            for (int ng = 0; ng < 4; ng++) {
                uint32_t bh[4];
                ldm4(bh, st + ST_B + boff[ng][ks]);
#pragma unroll
                for (int mt = 0; mt < 2; mt++) {
                    mma16816(acc[mt][2 * ng + 0], ah[mt], bh[0], bh[2]);
                    mma16816(acc[mt][2 * ng + 1], ah[mt], bh[1], bh[3]);
                }
            }
        }
        __syncthreads();
    }
#undef LOAD_STAGE

    const int i_ch = by >> 2;
    float* ob = out + (size_t)(i_ch * 128 + t) * 131072;
    const int rbase = (by & 3) * 128 + m0w + (lane >> 2);
    const int cbase = n0w + (lane & 3) * 2;
#pragma unroll
    for (int mt = 0; mt < 2; mt++) {
        const int r0 = rbase + mt * 16;
#pragma unroll
        for (int nt = 0; nt < 8; nt++) {
            const int c = cbase + nt * 8;
            float2 v0 = make_float2(acc[mt][nt][0], acc[mt][nt][1]);
            float2 v1 = make_float2(acc[mt][nt][2], acc[mt][nt][3]);
            __stcs((float2*)(ob + (size_t)r0 * 256 + c), v0);
            __stcs((float2*)(ob + (size_t)(r0 + 8) * 256 + c), v1);
        }
    }
}

// ---------------------------------------------------------------------------
extern "C" void kernel_launch(void* const* d_in, const int* in_sizes, int n_in,
                              void* d_out, int out_size) {
    const float* inp = (const float*)d_in[0];   // (8,64,1024)
    const float* A   = (const float*)d_in[1];   // (256,256)
    const float* Bv  = (const float*)d_in[2];   // (256,)
    float* out = (float*)d_out;

    cudaFuncSetAttribute(main_mma_kernel,
                         cudaFuncAttributeMaxDynamicSharedMemorySize, SMEM_SZ);
    cudaFuncSetAttribute(pow_mma_kernel,
                         cudaFuncAttributeMaxDynamicSharedMemorySize, PW_SMEM);

    init_a_kernel<<<256, 256>>>(A);
    for (int d = 1; d <= 64; d <<= 1)
        pow_mma_kernel<<<dim3(2, 2, d), 256, PW_SMEM>>>(d);

    v_kernel<<<128, 256>>>(Bv);
    b_limbs_kernel<<<128 * NCHUNK, 256>>>();
    s_kernel<<<dim3(512, 8), 256>>>(inp);
    for (int i = 0; i < 7; i++)                 // H[1..7] via Horner
        combine_step_kernel<<<dim3(8, 16), 256>>>(i);
    a_limbs_kernel<<<32 * NCHUNK, 256>>>(inp);

    main_mma_kernel<<<dim3(128, 32), 512, SMEM_SZ>>>(out);
}

// round 12
// speedup vs baseline: 1.7394x; 1.0107x over previous
#include <cuda_runtime.h>
#include <cuda_fp16.h>
#include <cuda_bf16.h>
#include <cstdint>

// ---------------------------------------------------------------------------
// HiPPO-LegT: chunked convolution + one big GEMM.
// Main GEMM: mma.sync fp16 single limb (Ah*Bh, fp32 acc) + causal skips.
// Pow chain (A^1..A^128): tensor-core 3-limb bf16, K in 2 chunks of 128
// (halved sync/latency phases), R row-major + ldmatrix.trans.
// Combine: Horner H[i+1] = H[i] (A^128)^T + S[i+1] on 32x32 fp32 tiles.
// ---------------------------------------------------------------------------

#define N_ST   256
#define T_CH   128
#define MAT    65536
#define NCHUNK 6
#define AB_BLK 16384              // bytes: 128 rows x 64 k fp16 (swizzled)
#define BB_BLK 32768              // bytes: 256 rows x 64 k fp16 (swizzled)

// main mma kernel smem: per stage [Ah 16K][B 32K], 3 stages
#define ST_B   16384
#define ST_SZ  49152
#define NSTG   3
#define SMEM_SZ (NSTG * ST_SZ)

// pow mma kernel smem: [Ph 32K][Pl 32K][Rh 32K][Rl 32K] (K-chunk = 128)
#define PW_PL  32768
#define PW_RH  65536
#define PW_RL  98304
#define PW_SMEM 131072

// ---- device scratch ----
__device__ __align__(256) float g_Apow[129 * MAT];     // A^1..A^128 at 1..128
__device__ __align__(256) float g_V[T_CH * N_ST];      // v_j = A^j B
__device__ __align__(256) float g_S[8 * 512 * N_ST];
__device__ __align__(256) float g_H[8 * 512 * N_ST];
__device__ __align__(256) __half g_Ah[(size_t)32 * NCHUNK * 8192];
__device__ __align__(256) __half g_Bh[(size_t)128 * NCHUNK * 16384];

// ---------------------------------------------------------------------------
__device__ __forceinline__ uint32_t smem_u32(const void* p) {
    uint32_t a;
    asm("{ .reg .u64 t; cvta.to.shared.u64 t, %1; cvt.u32.u64 %0, t; }" : "=r"(a) : "l"(p));
    return a;
}
__device__ __forceinline__ void cp16(uint32_t s, const void* g) {
    asm volatile("cp.async.cg.shared.global [%0], [%1], 16;" :: "r"(s), "l"(g));
}
#define CP_COMMIT() asm volatile("cp.async.commit_group;" ::: "memory")
#define CP_WAIT(n)  asm volatile("cp.async.wait_group %0;" :: "n"(n) : "memory")

__device__ __forceinline__ void ldm4(uint32_t* r, uint32_t addr) {
    asm volatile("ldmatrix.sync.aligned.m8n8.x4.shared.b16 {%0,%1,%2,%3}, [%4];"
                 : "=r"(r[0]), "=r"(r[1]), "=r"(r[2]), "=r"(r[3]) : "r"(addr));
}
__device__ __forceinline__ void ldm4t(uint32_t* r, uint32_t addr) {
    asm volatile("ldmatrix.sync.aligned.m8n8.x4.trans.shared.b16 {%0,%1,%2,%3}, [%4];"
                 : "=r"(r[0]), "=r"(r[1]), "=r"(r[2]), "=r"(r[3]) : "r"(addr));
}
__device__ __forceinline__ void mma16816(float* d, const uint32_t* a,
                                         uint32_t b0, uint32_t b1) {
    asm volatile(
        "mma.sync.aligned.m16n8k16.row.col.f32.f16.f16.f32 "
        "{%0,%1,%2,%3}, {%4,%5,%6,%7}, {%8,%9}, {%0,%1,%2,%3};"
        : "+f"(d[0]), "+f"(d[1]), "+f"(d[2]), "+f"(d[3])
        : "r"(a[0]), "r"(a[1]), "r"(a[2]), "r"(a[3]), "r"(b0), "r"(b1));
}
__device__ __forceinline__ void mmabf(float* d, const uint32_t* a,
                                      uint32_t b0, uint32_t b1) {
    asm volatile(
        "mma.sync.aligned.m16n8k16.row.col.f32.bf16.bf16.f32 "
        "{%0,%1,%2,%3}, {%4,%5,%6,%7}, {%8,%9}, {%0,%1,%2,%3};"
        : "+f"(d[0]), "+f"(d[1]), "+f"(d[2]), "+f"(d[3])
        : "r"(a[0]), "r"(a[1]), "r"(a[2]), "r"(a[3]), "r"(b0), "r"(b1));
}

__device__ __forceinline__ uint32_t swz(uint32_t off) { return off ^ ((off >> 3) & 0x70); }

__device__ __forceinline__ unsigned short hbits(float x) {
    __half h = __float2half_rn(x);
    return *reinterpret_cast<unsigned short*>(&h);
}
__device__ __forceinline__ unsigned short bfb(__nv_bfloat16 b) {
    return *reinterpret_cast<unsigned short*>(&b);
}

// ---------------------------------------------------------------------------
__global__ void init_a_kernel(const float* __restrict__ A) {
    int idx = blockIdx.x * blockDim.x + threadIdx.x;
    if (idx < MAT) g_Apow[MAT + idx] = A[idx];
}

// ---------------------------------------------------------------------------
// Tensor-core 256x256x256 fp32-in/out product tile via 3-limb bf16.
// C[128x128 tile at (by*128, bx*128)] = P @ R, all row-major 256x256.
// K processed in 2 chunks of 128. P: [m][k] panels (two 64-k panels of 16KB).
// R: row-major [k][n] panels (two 64-n panels of 16KB), ldmatrix.trans.
// 256 threads, 8 warps of 32x64.
// ---------------------------------------------------------------------------
__device__ void mma256_tile(const float* __restrict__ P,
                            const float* __restrict__ R,
                            float* __restrict__ C) {
    extern __shared__ char smem[];
    const uint32_t sb = smem_u32(smem);
    const int tid = threadIdx.x;
    const int wid = tid >> 5, lane = tid & 31;
    const int bm = blockIdx.y * 128;
    const int bn = blockIdx.x * 128;
    const int m0w = (wid & 3) * 32;
    const int n0w = (wid >> 2) * 64;                  // 0 or 64 -> R n-panel
    const uint32_t rpH = sb + PW_RH + (uint32_t)(n0w >> 6) * 16384;
    const uint32_t rpL = sb + PW_RL + (uint32_t)(n0w >> 6) * 16384;

    // A fragment offsets within a 64-k panel (ks&3 = k16-step inside panel)
    uint32_t aoff[2][4];
    {
        const uint32_t arow = (uint32_t)(m0w + (lane & 15)) * 128;
        const uint32_t khalf = (uint32_t)(lane >> 4) * 16;
#pragma unroll
        for (int mt = 0; mt < 2; mt++)
#pragma unroll
            for (int ks = 0; ks < 4; ks++)
                aoff[mt][ks] = swz(arow + (uint32_t)mt * 2048 + khalf + ks * 32);
    }
    // B fragment base offsets (trans): ks=0 bases; higher ks adds ks*2048
    // (valid because swz only mixes bits [6:4]<-[9:7], untouched by +ks*2048).
    uint32_t boff0[4];
    {
        const int i = lane & 7, jm = lane >> 3;
        const uint32_t kl = (uint32_t)(i + (jm & 1) * 8);
        const uint32_t nb = (uint32_t)((jm >> 1) * 8);
#pragma unroll
        for (int ng = 0; ng < 4; ng++)
            boff0[ng] = swz(kl * 128 + (uint32_t)(ng * 16 + nb) * 2);
    }

    float acc[2][8][4];
#pragma unroll
    for (int mt = 0; mt < 2; mt++)
#pragma unroll
        for (int nt = 0; nt < 8; nt++)
#pragma unroll
            for (int q = 0; q < 4; q++) acc[mt][nt][q] = 0.f;

    const int kq = (tid & 31) * 4;      // 0..124 (k offset for P, n offset for R)
    const int rr0 = tid >> 5;           // 0..7

    for (int kb = 0; kb < 256; kb += 128) {
        __syncthreads();   // protect smem from previous iteration's readers
        // P chunk: [r 0..127][k 0..127] -> Ph/Pl panels, packed uint2 writes
#pragma unroll
        for (int it = 0; it < 16; it++) {
            const int r = it * 8 + rr0;
            float4 f = *(const float4*)&P[(size_t)(bm + r) * 256 + kb + kq];
            float v[4] = {f.x, f.y, f.z, f.w};
            unsigned short h[4], l[4];
#pragma unroll
            for (int q = 0; q < 4; q++) {
                __nv_bfloat16 bh = __float2bfloat16(v[q]);
                h[q] = bfb(bh);
                l[q] = bfb(__float2bfloat16(v[q] - __bfloat162float(bh)));
            }
            uint2 ph, pl;
            ph.x = (uint32_t)h[0] | ((uint32_t)h[1] << 16);
            ph.y = (uint32_t)h[2] | ((uint32_t)h[3] << 16);
            pl.x = (uint32_t)l[0] | ((uint32_t)l[1] << 16);
            pl.y = (uint32_t)l[2] | ((uint32_t)l[3] << 16);
            const uint32_t off = (uint32_t)(kq >> 6) * 16384 +
                                 swz((uint32_t)(r * 128 + (kq & 63) * 2));
            *(uint2*)(smem + off) = ph;
            *(uint2*)(smem + PW_PL + off) = pl;
        }
        // R chunk: [k 0..127][n 0..127] row-major -> n-panels, packed uint2
#pragma unroll
        for (int it = 0; it < 16; it++) {
            const int k = it * 8 + rr0;
            float4 f = *(const float4*)&R[(size_t)(kb + k) * 256 + bn + kq];
            float v[4] = {f.x, f.y, f.z, f.w};
            unsigned short h[4], l[4];
#pragma unroll
            for (int q = 0; q < 4; q++) {
                __nv_bfloat16 bh = __float2bfloat16(v[q]);
                h[q] = bfb(bh);
                l[q] = bfb(__float2bfloat16(v[q] - __bfloat162float(bh)));
            }
            uint2 rh, rl;
            rh.x = (uint32_t)h[0] | ((uint32_t)h[1] << 16);
            rh.y = (uint32_t)h[2] | ((uint32_t)h[3] << 16);
            rl.x = (uint32_t)l[0] | ((uint32_t)l[1] << 16);
            rl.y = (uint32_t)l[2] | ((uint32_t)l[3] << 16);
            const uint32_t off = (uint32_t)(kq >> 6) * 16384 +
                                 swz((uint32_t)(k * 128 + (kq & 63) * 2));
            *(uint2*)(smem + PW_RH + off) = rh;
            *(uint2*)(smem + PW_RL + off) = rl;
        }
        __syncthreads();
#pragma unroll
        for (int ks = 0; ks < 8; ks++) {
            const uint32_t pbase = sb + (uint32_t)(ks >> 2) * 16384;
            const uint32_t rk = (uint32_t)ks * 2048;
            uint32_t ah[2][4], al[2][4];
#pragma unroll
            for (int mt = 0; mt < 2; mt++) {
                ldm4(ah[mt], pbase + aoff[mt][ks & 3]);
                ldm4(al[mt], pbase + PW_PL + aoff[mt][ks & 3]);
            }
#pragma unroll
            for (int ng = 0; ng < 4; ng++) {
                uint32_t bh[4], bl[4];
                ldm4t(bh, rpH + rk + boff0[ng]);
                ldm4t(bl, rpL + rk + boff0[ng]);
#pragma unroll
                for (int mt = 0; mt < 2; mt++) {
                    mmabf(acc[mt][2 * ng + 0], ah[mt], bh[0], bh[1]);
                    mmabf(acc[mt][2 * ng + 1], ah[mt], bh[2], bh[3]);
                    mmabf(acc[mt][2 * ng + 0], ah[mt], bl[0], bl[1]);
                    mmabf(acc[mt][2 * ng + 1], ah[mt], bl[2], bl[3]);
                    mmabf(acc[mt][2 * ng + 0], al[mt], bh[0], bh[1]);
                    mmabf(acc[mt][2 * ng + 1], al[mt], bh[2], bh[3]);
                }
            }
        }
    }

    const int rbase = bm + m0w + (lane >> 2);
    const int cbase = bn + n0w + (lane & 3) * 2;
#pragma unroll
    for (int mt = 0; mt < 2; mt++) {
        const int r0 = rbase + mt * 16;
#pragma unroll
        for (int nt = 0; nt < 8; nt++) {
            const int c = cbase + nt * 8;
            *(float2*)&C[(size_t)r0 * 256 + c] =
                make_float2(acc[mt][nt][0], acc[mt][nt][1]);
            *(float2*)&C[(size_t)(r0 + 8) * 256 + c] =
                make_float2(acc[mt][nt][2], acc[mt][nt][3]);
        }
    }
}

// A^{d+j} = A^d @ A^j for j = 1..d   grid (2, 2, d), 256 threads, 128KB smem
__global__ __launch_bounds__(256) void pow_mma_kernel(int d) {
    const int j = blockIdx.z + 1;
    mma256_tile(g_Apow + (size_t)d * MAT, g_Apow + (size_t)j * MAT,
                g_Apow + (size_t)(d + j) * MAT);
}

// ---------------------------------------------------------------------------
// fp32 32x32-tile GEMM (Horner combine): C = Am @ Bt^T + bias
// ---------------------------------------------------------------------------
__device__ __forceinline__ void gemm32_ntr(const float* __restrict__ Am,
                                           const float* __restrict__ Bt,
                                           float* __restrict__ Cm,
                                           const float* __restrict__ bias,
                                           int brow, int bcol) {
    __shared__ float As[16][33];
    __shared__ float Bs[16][33];
    const int tid = threadIdx.x;
    const int ty = tid >> 4, tx = tid & 15;
    const int ar = tid >> 3;            // 0..31
    const int ak = (tid & 7) * 2;       // 0..14
    float acc[2][2] = {};
    for (int k0 = 0; k0 < 256; k0 += 16) {
        float2 a2 = *(const float2*)&Am[(size_t)(brow + ar) * 256 + k0 + ak];
        As[ak][ar] = a2.x; As[ak + 1][ar] = a2.y;
        float2 b2 = *(const float2*)&Bt[(size_t)(bcol + ar) * 256 + k0 + ak];
        Bs[ak][ar] = b2.x; Bs[ak + 1][ar] = b2.y;
        __syncthreads();
#pragma unroll
        for (int k = 0; k < 16; k++) {
            float a0 = As[k][ty * 2], a1 = As[k][ty * 2 + 1];
            float b0 = Bs[k][tx * 2], b1 = Bs[k][tx * 2 + 1];
            acc[0][0] += a0 * b0; acc[0][1] += a0 * b1;
            acc[1][0] += a1 * b0; acc[1][1] += a1 * b1;
        }
        __syncthreads();
    }
#pragma unroll
    for (int ii = 0; ii < 2; ii++) {
        const size_t off = (size_t)(brow + ty * 2 + ii) * 256 + bcol + tx * 2;
        float2 b = *(const float2*)&bias[off];
        float2 v = make_float2(acc[ii][0] + b.x, acc[ii][1] + b.y);
        *(float2*)&Cm[off] = v;
    }
}

// Horner: H[i+1] = H[i] @ (A^128)^T + S[i+1]   grid (8, 16)
__global__ void combine_step_kernel(int i) {
    gemm32_ntr(g_H + (size_t)i * (512 * 256),
               g_Apow + (size_t)128 * MAT,
               g_H + (size_t)(i + 1) * (512 * 256),
               g_S + (size_t)(i + 1) * (512 * 256),
               blockIdx.y * 32, blockIdx.x * 32);
}

__global__ void v_kernel(const float* __restrict__ Bv) {
    __shared__ float bs[256];
    int j = blockIdx.x, n = threadIdx.x;
    bs[n] = Bv[n];
    __syncthreads();
    if (j == 0) { g_V[n] = bs[n]; return; }
    const float* Am = g_Apow + (size_t)j * MAT;
    float s = 0.f;
#pragma unroll 8
    for (int m = 0; m < 256; m++) s += Am[n * 256 + m] * bs[m];
    g_V[j * 256 + n] = s;
}

__global__ void s_kernel(const float* __restrict__ inp) {
    __shared__ float fs[128];
    int r = blockIdx.x, i = blockIdx.y, n = threadIdx.x;
    if (n < 128) fs[n] = inp[r * 1024 + i * T_CH + n];
    __syncthreads();
    float s = 0.f;
#pragma unroll 4
    for (int k = 0; k < 128; k++)
        s += g_V[(127 - k) * 256 + n] * fs[k];
    g_S[(i * 512 + r) * 256 + n] = s;
    if (i == 0) g_H[r * 256 + n] = s;   // H[0] = S[0]
}

// ---------------------------------------------------------------------------
// packers (fp16 single limb), SW128-swizzled, exact smem image.
// ---------------------------------------------------------------------------
__global__ void b_limbs_kernel() {
    const int blk = blockIdx.x;            // t*6 + kc
    const int t = blk / NCHUNK, kc = blk % NCHUNK;
    const int tid = threadIdx.x;
    const int kk0 = (tid & 15) * 4;
    char* dh = (char*)g_Bh + (size_t)blk * BB_BLK;
    for (int it = 0; it < 16; it++) {
        int n = it * 16 + (tid >> 4);
        float v[4];
        if (kc < 2) {
            int k0 = kc * 64 + kk0;
#pragma unroll
            for (int q = 0; q < 4; q++) {
                int k = k0 + q;
                v[q] = (k <= t) ? g_V[(t - k) * 256 + n] : 0.f;
            }
        } else {
            int m0 = kc * 64 + kk0 - 128;
            float4 a4 = *(const float4*)&g_Apow[(size_t)(t + 1) * MAT + n * 256 + m0];
            v[0] = a4.x; v[1] = a4.y; v[2] = a4.z; v[3] = a4.w;
        }
        uint2 ph;
        ph.x = (uint32_t)hbits(v[0]) | ((uint32_t)hbits(v[1]) << 16);
        ph.y = (uint32_t)hbits(v[2]) | ((uint32_t)hbits(v[3]) << 16);
        uint32_t off = swz((uint32_t)(n * 128 + kk0 * 2));
        *(uint2*)(dh + off) = ph;
    }
}

__global__ void a_limbs_kernel(const float* __restrict__ inp) {
    const int blk = blockIdx.x;            // rt*6 + kc
    const int rt = blk / NCHUNK, kc = blk % NCHUNK;
    const int i = rt >> 2;
    const int tid = threadIdx.x;
    const int kk0 = (tid & 15) * 4;
    char* dh = (char*)g_Ah + (size_t)blk * AB_BLK;
    for (int it = 0; it < 8; it++) {
        int row = it * 16 + (tid >> 4);
        int r = (rt & 3) * 128 + row;
        float v[4];
        if (kc < 2) {
            float4 f4 = *(const float4*)&inp[r * 1024 + i * 128 + kc * 64 + kk0];
            v[0] = f4.x; v[1] = f4.y; v[2] = f4.z; v[3] = f4.w;
        } else if (i == 0) {
            v[0] = v[1] = v[2] = v[3] = 0.f;
        } else {
            float4 f4 = *(const float4*)&g_H[(size_t)((i - 1) * 512 + r) * 256 +
                                             (kc - 2) * 64 + kk0];
            v[0] = f4.x; v[1] = f4.y; v[2] = f4.z; v[3] = f4.w;
        }
        uint2 ph;
        ph.x = (uint32_t)hbits(v[0]) | ((uint32_t)hbits(v[1]) << 16);
        ph.y = (uint32_t)hbits(v[2]) | ((uint32_t)hbits(v[3]) << 16);
        uint32_t off = swz((uint32_t)(row * 128 + kk0 * 2));
        *(uint2*)(dh + off) = ph;
    }
}

// ---------------------------------------------------------------------------
// Main GEMM: fp16 SINGLE-limb mma.sync. CTA = 128x256 out tile, 512 threads
// (16 warps, 32x64 warp tiles), 3-stage cp.async pipeline. Causal skip at
// chunk level (kc=1 for t<64) AND k16-step level inside W-chunks.
// grid (128 t-tiles, 32 row tiles).     [unchanged — passing since round 8]
// ---------------------------------------------------------------------------
__global__ __launch_bounds__(512, 1) void main_mma_kernel(float* __restrict__ out) {
    extern __shared__ char smem[];
    const uint32_t sb = smem_u32(smem);
    const int tid = threadIdx.x;
    const int wid = tid >> 5;
    const int lane = tid & 31;
    const int t = blockIdx.x;
    const int by = blockIdx.y;

    const int m0w = (wid & 3) * 32;
    const int n0w = (wid >> 2) * 64;

    int clist[6] = {0, 1, 2, 3, 4, 5};
    int nch = 6;
    if (t < 64) { clist[1] = 2; clist[2] = 3; clist[3] = 4; clist[4] = 5; nch = 5; }

    const int nks_c0 = min(4, (t >> 4) + 1);
    const int nks_c1 = (t < 64) ? 0 : min(4, ((t - 64) >> 4) + 1);

    const char* Asrc = (const char*)g_Ah + (size_t)by * NCHUNK * AB_BLK;
    const char* Bsrc = (const char*)g_Bh + (size_t)t * NCHUNK * BB_BLK;

    const uint32_t cpo = (uint32_t)tid * 16;

    uint32_t aoff[2][4];
    uint32_t boff[4][4];
    {
        const uint32_t arow = (uint32_t)(m0w + (lane & 15)) * 128;
        const uint32_t khalf = (uint32_t)(lane >> 4) * 16;
#pragma unroll
        for (int mt = 0; mt < 2; mt++)
#pragma unroll
            for (int ks = 0; ks < 4; ks++)
                aoff[mt][ks] = swz(arow + (uint32_t)mt * 2048 + khalf + ks * 32);
        const uint32_t brow = (uint32_t)(n0w + (lane & 15)) * 128;
#pragma unroll
        for (int ng = 0; ng < 4; ng++)
#pragma unroll
            for (int ks = 0; ks < 4; ks++)
                boff[ng][ks] = swz(brow + (uint32_t)ng * 2048 + khalf + ks * 32);
    }

    float acc[2][8][4];
#pragma unroll
    for (int mt = 0; mt < 2; mt++)
#pragma unroll
        for (int nt = 0; nt < 8; nt++)
#pragma unroll
            for (int q = 0; q < 4; q++) acc[mt][nt][q] = 0.f;

#define LOAD_STAGE(kc, st)                                                      \
    do {                                                                        \
        uint32_t s0 = sb + (uint32_t)(st) * ST_SZ;                              \
        const char* ga = Asrc + (size_t)(kc) * AB_BLK;                          \
        const char* gc = Bsrc + (size_t)(kc) * BB_BLK;                          \
        cp16(s0 + cpo, ga + cpo);                                               \
        cp16(s0 + 8192 + cpo, ga + 8192 + cpo);                                 \
        _Pragma("unroll")                                                       \
        for (int q = 0; q < 4; q++)                                             \
            cp16(s0 + ST_B + q * 8192 + cpo, gc + q * 8192 + cpo);              \
        CP_COMMIT();                                                            \
    } while (0)

    LOAD_STAGE(clist[0], 0);
    LOAD_STAGE(clist[1], 1);

    for (int j = 0; j < nch; j++) {
        if (j + NSTG - 1 < nch) {
            LOAD_STAGE(clist[j + NSTG - 1], (j + NSTG - 1) % NSTG);
            CP_WAIT(2);
        } else if (j == nch - 2) {
            CP_WAIT(1);
        } else {
            CP_WAIT(0);
        }
        __syncthreads();
        const uint32_t st = sb + (uint32_t)(j % NSTG) * ST_SZ;
        const int kc = clist[j];
        const int nks = (kc == 0) ? nks_c0 : ((kc == 1) ? nks_c1 : 4);
#pragma unroll
        for (int ks = 0; ks < 4; ks++) {
            if (ks >= nks) break;
            uint32_t ah[2][4];
            ldm4(ah[0], st + aoff[0][ks]);
            ldm4(ah[1], st + aoff[1][ks]);
#pragma unroll
            for (int ng = 0; ng < 4; ng++) {
                uint32_t bh[4];
                ldm4(bh, st + ST_B + boff[ng][ks]);
#pragma unroll
                for (int mt = 0; mt < 2; mt++) {
                    mma16816(acc[mt][2 * ng + 0], ah[mt], bh[0], bh[2]);
                    mma16816(acc[mt][2 * ng + 1], ah[mt], bh[1], bh[3]);
                }
            }
        }
        __syncthreads();
    }
#undef LOAD_STAGE

    const int i_ch = by >> 2;
    float* ob = out + (size_t)(i_ch * 128 + t) * 131072;
    const int rbase = (by & 3) * 128 + m0w + (lane >> 2);
    const int cbase = n0w + (lane & 3) * 2;
#pragma unroll
    for (int mt = 0; mt < 2; mt++) {
        const int r0 = rbase + mt * 16;
#pragma unroll
        for (int nt = 0; nt < 8; nt++) {
            const int c = cbase + nt * 8;
            float2 v0 = make_float2(acc[mt][nt][0], acc[mt][nt][1]);
            float2 v1 = make_float2(acc[mt][nt][2], acc[mt][nt][3]);
            __stcs((float2*)(ob + (size_t)r0 * 256 + c), v0);
            __stcs((float2*)(ob + (size_t)(r0 + 8) * 256 + c), v1);
        }
    }
}

// ---------------------------------------------------------------------------
extern "C" void kernel_launch(void* const* d_in, const int* in_sizes, int n_in,
                              void* d_out, int out_size) {
    const float* inp = (const float*)d_in[0];   // (8,64,1024)
    const float* A   = (const float*)d_in[1];   // (256,256)
    const float* Bv  = (const float*)d_in[2];   // (256,)
    float* out = (float*)d_out;

    cudaFuncSetAttribute(main_mma_kernel,
                         cudaFuncAttributeMaxDynamicSharedMemorySize, SMEM_SZ);
    cudaFuncSetAttribute(pow_mma_kernel,
                         cudaFuncAttributeMaxDynamicSharedMemorySize, PW_SMEM);

    init_a_kernel<<<256, 256>>>(A);
    for (int d = 1; d <= 64; d <<= 1)
        pow_mma_kernel<<<dim3(2, 2, d), 256, PW_SMEM>>>(d);

    v_kernel<<<128, 256>>>(Bv);
    b_limbs_kernel<<<128 * NCHUNK, 256>>>();
    s_kernel<<<dim3(512, 8), 256>>>(inp);
    for (int i = 0; i < 7; i++)                 // H[1..7] via Horner
        combine_step_kernel<<<dim3(8, 16), 256>>>(i);
    a_limbs_kernel<<<32 * NCHUNK, 256>>>(inp);

    main_mma_kernel<<<dim3(128, 32), 512, SMEM_SZ>>>(out);
}